// round 8
// baseline (speedup 1.0000x reference)
#include <cuda_runtime.h>
#include <cuda_bf16.h>
#include <cstdint>
#include <math.h>

// ---------------- problem constants ----------------
#define B_    32
#define N_    577
#define C_    768
#define H_    12
#define D_    64
#define GRID_ 24
#define RAD_  3
#define K_    768
#define M_    (B_*N_)      // 18464
#define MT_   145          // ceil(M/128)
#define MPAD_ (MT_*128)    // 18560

// ---------------- device-global scratch ----------------
__device__ __nv_bfloat16 g_xhi[MPAD_*K_];
__device__ __nv_bfloat16 g_xlo[MPAD_*K_];
__device__ __nv_bfloat16 g_Whi[3*C_*K_];   // Wqkv^T  [2304,768]
__device__ __nv_bfloat16 g_Wlo[3*C_*K_];
__device__ __nv_bfloat16 g_Phi[C_*K_];     // Wproj^T [768,768]
__device__ __nv_bfloat16 g_Plo[C_*K_];
__device__ float         g_QKV[(size_t)M_*3*C_];      // [m, 2304]
__device__ __nv_bfloat16 g_Ohi[MPAD_*C_];
__device__ __nv_bfloat16 g_Olo[MPAD_*C_];

// ---------------- PTX helpers ----------------
__device__ __forceinline__ uint32_t smem_u32(const void* p) {
    uint32_t a;
    asm("{ .reg .u64 t; cvta.to.shared.u64 t, %1; cvt.u32.u64 %0, t; }" : "=r"(a) : "l"(p));
    return a;
}
__device__ __forceinline__ void cp_async16(uint32_t dst, const void* src) {
    asm volatile("cp.async.cg.shared.global [%0], [%1], 16;" :: "r"(dst), "l"(src));
}
__device__ __forceinline__ void cp_commit() {
    asm volatile("cp.async.commit_group;");
}
template <int NN>
__device__ __forceinline__ void cp_wait() {
    asm volatile("cp.async.wait_group %0;" :: "n"(NN));
}
__device__ __forceinline__ void ldmatrix_x4(uint32_t& r0, uint32_t& r1,
                                            uint32_t& r2, uint32_t& r3, uint32_t addr) {
    asm volatile("ldmatrix.sync.aligned.m8n8.x4.shared.b16 {%0,%1,%2,%3}, [%4];"
                 : "=r"(r0), "=r"(r1), "=r"(r2), "=r"(r3) : "r"(addr));
}
__device__ __forceinline__ void mma_bf16(float* c, const uint32_t* a,
                                         uint32_t b0, uint32_t b1) {
    asm volatile(
        "mma.sync.aligned.m16n8k16.row.col.f32.bf16.bf16.f32 "
        "{%0,%1,%2,%3}, {%4,%5,%6,%7}, {%8,%9}, {%0,%1,%2,%3};"
        : "+f"(c[0]), "+f"(c[1]), "+f"(c[2]), "+f"(c[3])
        : "r"(a[0]), "r"(a[1]), "r"(a[2]), "r"(a[3]), "r"(b0), "r"(b1));
}

// ============================================================================
// conversion kernels
// ============================================================================
__global__ void conv_x_kernel(const float* __restrict__ x) {
    size_t idx = (size_t)blockIdx.x * 256 + threadIdx.x;
    if (idx >= (size_t)MPAD_ * K_) return;
    size_t m = idx / K_;
    if (m < M_) {
        float a = x[idx];
        __nv_bfloat16 hi = __float2bfloat16(a);
        __nv_bfloat16 lo = __float2bfloat16(a - __bfloat162float(hi));
        g_xhi[idx] = hi;
        g_xlo[idx] = lo;
    } else {
        g_xhi[idx] = __float2bfloat16(0.f);
        g_xlo[idx] = __float2bfloat16(0.f);
        g_Ohi[idx] = __float2bfloat16(0.f);
        g_Olo[idx] = __float2bfloat16(0.f);
    }
}

__global__ void conv_wT_kernel(const float* __restrict__ W,
                               __nv_bfloat16* __restrict__ Thi,
                               __nv_bfloat16* __restrict__ Tlo, int Ncols) {
    __shared__ float t[32][33];
    const int kc = blockIdx.y * 32;
    const int nc = blockIdx.x * 32;
    const int tx = threadIdx.x & 31;
    const int ty = threadIdx.x >> 5;
    for (int i = ty; i < 32; i += 8)
        t[i][tx] = W[(size_t)(kc + i) * Ncols + nc + tx];
    __syncthreads();
    for (int i = ty; i < 32; i += 8) {
        float a = t[tx][i];
        __nv_bfloat16 hi = __float2bfloat16(a);
        __nv_bfloat16 lo = __float2bfloat16(a - __bfloat162float(hi));
        size_t o = (size_t)(nc + i) * K_ + kc + tx;
        Thi[o] = hi;
        Tlo[o] = lo;
    }
}

// ============================================================================
// split-bf16 HMMA GEMM: 128x64x64 tiles, 2-stage cp.async, 2 CTAs/SM
// (unchanged from R7 measurement: 441.9us)
// ============================================================================
#define NCHUNK   (K_/64)          // 12
#define A_B      (128*128)
#define B_B      (64*128)
#define STAGE_B  (2*A_B + 2*B_B)  // 48KB
#define GEMM_SMEM (2*STAGE_B)     // 96KB

__global__ __launch_bounds__(256, 2)
void hmma_gemm_kernel(const __nv_bfloat16* __restrict__ Ahi,
                      const __nv_bfloat16* __restrict__ Alo,
                      const __nv_bfloat16* __restrict__ Bhi,
                      const __nv_bfloat16* __restrict__ Blo,
                      const float* __restrict__ bias,
                      float* __restrict__ Cout,
                      int Ncols, int Mrows)
{
    extern __shared__ unsigned char smem[];
    const uint32_t s_base = smem_u32(smem);

    const int tid   = threadIdx.x;
    const int wid   = tid >> 5;
    const int lane  = tid & 31;
    const int m0    = blockIdx.y * 128;
    const int n0    = blockIdx.x * 64;
    const int wm    = (wid >> 1) * 32;
    const int wn    = (wid & 1) * 32;

    const int lr = tid >> 3;
    const int lc = tid & 7;
    auto load_stage = [&](int st, int kc) {
        const uint32_t sb = s_base + st * STAGE_B;
        const int k0 = kc * 64 + lc * 8;
#pragma unroll
        for (int i = 0; i < 4; i++) {
            const int row = lr + i * 32;
            const uint32_t so = row * 128 + ((lc ^ (row & 7)) << 4);
            const size_t ga = (size_t)(m0 + row) * K_ + k0;
            cp_async16(sb + so,        Ahi + ga);
            cp_async16(sb + A_B + so,  Alo + ga);
        }
#pragma unroll
        for (int i = 0; i < 2; i++) {
            const int row = lr + i * 32;
            const uint32_t so = row * 128 + ((lc ^ (row & 7)) << 4);
            const size_t gb = (size_t)(n0 + row) * K_ + k0;
            cp_async16(sb + 2*A_B + so,        Bhi + gb);
            cp_async16(sb + 2*A_B + B_B + so,  Blo + gb);
        }
    };

    float acc[2][4][4];
#pragma unroll
    for (int i = 0; i < 2; i++)
#pragma unroll
        for (int j = 0; j < 4; j++)
#pragma unroll
            for (int v = 0; v < 4; v++) acc[i][j][v] = 0.f;

    load_stage(0, 0); cp_commit();

    const int a_row = (lane & 15);
    const int a_chi = (lane >> 4);
    const int b_row = (lane & 7) + ((lane >> 4) << 3);
    const int b_chi = (lane >> 3) & 1;

    for (int kc = 0; kc < NCHUNK; kc++) {
        if (kc + 1 < NCHUNK) {
            load_stage((kc + 1) & 1, kc + 1);
            cp_commit();
            cp_wait<1>();
        } else {
            cp_wait<0>();
        }
        __syncthreads();

        const uint32_t sb   = s_base + (kc & 1) * STAGE_B;
        const uint32_t sAhi = sb;
        const uint32_t sAlo = sb + A_B;
        const uint32_t sBhi = sb + 2*A_B;
        const uint32_t sBlo = sb + 2*A_B + B_B;

#pragma unroll
        for (int s = 0; s < 4; s++) {
            uint32_t fah[2][4], fal[2][4];
#pragma unroll
            for (int mi = 0; mi < 2; mi++) {
                const int row = wm + mi * 16 + a_row;
                const int ch  = (2 * s + a_chi) ^ (row & 7);
                const uint32_t off = row * 128 + (ch << 4);
                ldmatrix_x4(fah[mi][0], fah[mi][1], fah[mi][2], fah[mi][3], sAhi + off);
                ldmatrix_x4(fal[mi][0], fal[mi][1], fal[mi][2], fal[mi][3], sAlo + off);
            }
            uint32_t fbh[2][4], fbl[2][4];
#pragma unroll
            for (int ng = 0; ng < 2; ng++) {
                const int row = wn + ng * 16 + b_row;
                const int ch  = (2 * s + b_chi) ^ (row & 7);
                const uint32_t off = row * 128 + (ch << 4);
                ldmatrix_x4(fbh[ng][0], fbh[ng][1], fbh[ng][2], fbh[ng][3], sBhi + off);
                ldmatrix_x4(fbl[ng][0], fbl[ng][1], fbl[ng][2], fbl[ng][3], sBlo + off);
            }
#pragma unroll
            for (int mi = 0; mi < 2; mi++) {
#pragma unroll
                for (int ng = 0; ng < 2; ng++) {
#pragma unroll
                    for (int hh = 0; hh < 2; hh++) {
                        float* c = acc[mi][ng * 2 + hh];
                        const uint32_t bh0 = fbh[ng][hh * 2], bh1 = fbh[ng][hh * 2 + 1];
                        const uint32_t bl0 = fbl[ng][hh * 2], bl1 = fbl[ng][hh * 2 + 1];
                        mma_bf16(c, fah[mi], bh0, bh1);
                        mma_bf16(c, fah[mi], bl0, bl1);
                        mma_bf16(c, fal[mi], bh0, bh1);
                    }
                }
            }
        }
        __syncthreads();
    }

#pragma unroll
    for (int ni = 0; ni < 4; ni++) {
        const int col = n0 + wn + ni * 8 + (lane & 3) * 2;
        const float bx = bias ? bias[col]     : 0.f;
        const float by = bias ? bias[col + 1] : 0.f;
#pragma unroll
        for (int mi = 0; mi < 2; mi++) {
            const int r0 = m0 + wm + mi * 16 + (lane >> 2);
            if (r0 < Mrows) {
                float2 v = make_float2(acc[mi][ni][0] + bx, acc[mi][ni][1] + by);
                *(float2*)(Cout + (size_t)r0 * Ncols + col) = v;
            }
            const int r1 = r0 + 8;
            if (r1 < Mrows) {
                float2 v = make_float2(acc[mi][ni][2] + bx, acc[mi][ni][3] + by);
                *(float2*)(Cout + (size_t)r1 * Ncols + col) = v;
            }
        }
    }
}

// ============================================================================
// attention: sliding-window CTA per (b,h) + CLS CTAs
//   blk < B*H : sliding local CTA; 8-row K/V ring in smem, 24 steps
//   blk >= B*H: CLS CTA (dense 577 keys)
// ring layout: slot 0 = CLS; grid row rr -> slots 1+(rr&7)*24 .. +23
// ============================================================================
#define RING_SLOTS (1 + 8*GRID_)     // 193
#define KSTR       68
#define RING_F     (RING_SLOTS*KSTR) // 13124 floats
#define SQ_F       (24*64)           // 1536
#define PROBS_F    (8*64)            // 512
#define ATT_SMEM   ((2*RING_F + SQ_F + PROBS_F)*4)   // 113,184 B

__global__ __launch_bounds__(256)
void attn_kernel()
{
    extern __shared__ float sm[];

    const int tid  = threadIdx.x;
    const int lane = tid & 31;
    const int warp = tid >> 5;
    const int blk  = blockIdx.x;

    if (blk < B_ * H_) {
        // ---------------- sliding-window local CTA ----------------
        float* sK    = sm;
        float* sV    = sm + RING_F;
        float* sQ    = sm + 2 * RING_F;
        float* sProb = sQ + SQ_F;
        const uint32_t aK = smem_u32(sK);
        const uint32_t aV = smem_u32(sV);
        const uint32_t aQ = smem_u32(sQ);

        const int b = blk / H_;
        const int h = blk % H_;
        const size_t base = (size_t)b * N_ * (3 * C_);
        const int qoff = h * D_;
        const int koff = C_ + h * D_;
        const int voff = 2 * C_ + h * D_;

        // ---- async loaders ----
        auto load_row = [&](int rr) {   // K+V of grid row rr -> ring
            for (int i = tid; i < GRID_ * 16; i += 256) {
                const int cc = i >> 4, part = i & 15;
                const float* gp = g_QKV + base + (size_t)(1 + rr * GRID_ + cc) * (3 * C_);
                const uint32_t so = (uint32_t)((1 + (rr & 7) * GRID_ + cc) * KSTR + part * 4) * 4;
                cp_async16(aK + so, gp + koff + part * 4);
                cp_async16(aV + so, gp + voff + part * 4);
            }
        };
        auto load_q = [&](int r) {
            for (int i = tid; i < GRID_ * 16; i += 256) {
                const int c = i >> 4, part = i & 15;
                const float* gp = g_QKV + base + (size_t)(1 + r * GRID_ + c) * (3 * C_);
                cp_async16(aQ + (uint32_t)(c * 64 + part * 4) * 4, gp + qoff + part * 4);
            }
        };

        // ---- prologue: CLS + rows 0..3 + q row 0 ----
        if (tid < 16) {
            const float* gp = g_QKV + base;   // key 0
            const uint32_t so = (uint32_t)(tid * 4) * 4;
            cp_async16(aK + so, gp + koff + tid * 4);
            cp_async16(aV + so, gp + voff + tid * 4);
        }
        load_row(0); load_row(1); load_row(2); load_row(3);
        load_q(0);
        cp_commit();
        cp_wait<0>();
        __syncthreads();

        for (int r = 0; r < GRID_; r++) {
            // prefetch row r+4 while computing
            if (r + 4 < GRID_) load_row(r + 4);
            cp_commit();

            const int r0   = (r - RAD_ < 0) ? 0 : r - RAD_;
            const int r1   = (r + RAD_ > GRID_ - 1) ? GRID_ - 1 : r + RAD_;
            const int span = r1 - r0 + 1;

            for (int c = warp; c < GRID_; c += 8) {
                const int c0 = (c - RAD_ < 0) ? 0 : c - RAD_;
                const int c1 = (c + RAD_ > GRID_ - 1) ? GRID_ - 1 : c + RAD_;
                const int cw = c1 - c0 + 1;
                const int cnt = 1 + span * cw;

                // lane -> key slot (ring)
                int slot0 = 0, slot1 = 0;
                if (lane > 0 && lane < cnt) {
                    const int j = lane - 1;
                    slot0 = 1 + ((r0 + j / cw) & 7) * GRID_ + (c0 + j % cw);
                }
                if (lane + 32 < cnt) {
                    const int j = lane + 31;
                    slot1 = 1 + ((r0 + j / cw) & 7) * GRID_ + (c0 + j % cw);
                }
                const float4* q4  = (const float4*)(sQ + c * 64);
                const float4* kr0 = (const float4*)(sK + slot0 * KSTR);
                const float4* kr1 = (const float4*)(sK + slot1 * KSTR);
                float acc0 = 0.f, acc1 = 0.f;
#pragma unroll
                for (int i = 0; i < 16; i++) {
                    const float4 qv = q4[i];
                    const float4 k0 = kr0[i];
                    const float4 k1 = kr1[i];
                    acc0 += qv.x * k0.x + qv.y * k0.y + qv.z * k0.z + qv.w * k0.w;
                    acc1 += qv.x * k1.x + qv.y * k1.y + qv.z * k1.z + qv.w * k1.w;
                }
                float s0 = (lane < cnt)      ? acc0 * 0.125f : -1e30f;
                float s1 = (lane + 32 < cnt) ? acc1 * 0.125f : -1e30f;

                float mx = fmaxf(s0, s1);
#pragma unroll
                for (int off = 16; off; off >>= 1)
                    mx = fmaxf(mx, __shfl_xor_sync(0xffffffffu, mx, off));
                const float e0 = __expf(s0 - mx);
                const float e1 = __expf(s1 - mx);
                float sum = e0 + e1;
#pragma unroll
                for (int off = 16; off; off >>= 1)
                    sum += __shfl_xor_sync(0xffffffffu, sum, off);
                const float inv = 1.0f / sum;

                sProb[warp * 64 + lane]      = e0 * inv;
                sProb[warp * 64 + lane + 32] = e1 * inv;
                __syncwarp();

                // AV with direct ring addressing (no indirection)
                const float* wp = sProb + warp * 64;
                float a0, a1;
                {   // CLS key (slot 0)
                    const float p = wp[0];
                    const float2 v = *(const float2*)(sV + 2 * lane);
                    a0 = p * v.x;
                    a1 = p * v.y;
                }
                int idx = 1;
                for (int rr = r0; rr <= r1; rr++) {
                    const int rowb = 1 + (rr & 7) * GRID_;
#pragma unroll 4
                    for (int cc = c0; cc <= c1; cc++) {
                        const float p = wp[idx++];
                        const float2 v = *(const float2*)(sV + (rowb + cc) * KSTR + 2 * lane);
                        a0 = fmaf(p, v.x, a0);
                        a1 = fmaf(p, v.y, a1);
                    }
                }

                const int n = 1 + r * GRID_ + c;
                const size_t o = ((size_t)b * N_ + n) * C_ + h * D_ + 2 * lane;
                const __nv_bfloat16 h0 = __float2bfloat16(a0);
                const __nv_bfloat16 h1 = __float2bfloat16(a1);
                __nv_bfloat162 hp; hp.x = h0; hp.y = h1;
                __nv_bfloat162 lp;
                lp.x = __float2bfloat16(a0 - __bfloat162float(h0));
                lp.y = __float2bfloat16(a1 - __bfloat162float(h1));
                *(__nv_bfloat162*)(g_Ohi + o) = hp;
                *(__nv_bfloat162*)(g_Olo + o) = lp;
                __syncwarp();
            }

            cp_wait<0>();        // row r+4 arrived
            __syncthreads();     // all warps done with sQ
            if (r + 1 < GRID_) {
                load_q(r + 1);
                cp_commit();
                cp_wait<0>();
            }
            __syncthreads();
        }
    } else {
        // ---------------- CLS CTA ----------------
        float* scores = sm;                 // [577] (+pad)
        float* partA  = sm + 640;           // [8][64]
        float* red    = sm + 640 + 8 * 64;  // [8]

        const int w2 = blk - B_ * H_;
        const int b  = w2 / H_;
        const int h  = w2 % H_;

        const size_t rowm = (size_t)b * N_;   // n = 0
        const float* qp = g_QKV + rowm * (3 * C_) + h * D_;
        const float q0 = qp[lane];
        const float q1 = qp[lane + 32];

        const size_t krow0 = (size_t)b * N_ * (3 * C_);
        const int koff = C_ + h * D_;
        const int voff = 2 * C_ + h * D_;

        for (int j = warp; j < N_; j += 8) {
            const float* kp = g_QKV + krow0 + (size_t)j * (3 * C_) + koff;
            float s = q0 * kp[lane] + q1 * kp[lane + 32];
#pragma unroll
            for (int off = 16; off; off >>= 1)
                s += __shfl_xor_sync(0xffffffffu, s, off);
            if (lane == 0) scores[j] = s * 0.125f;
        }
        __syncthreads();

        float mx = -1e30f;
        for (int i = tid; i < N_; i += 256) mx = fmaxf(mx, scores[i]);
#pragma unroll
        for (int off = 16; off; off >>= 1)
            mx = fmaxf(mx, __shfl_xor_sync(0xffffffffu, mx, off));
        if (lane == 0) red[warp] = mx;
        __syncthreads();
        mx = red[0];
#pragma unroll
        for (int w = 1; w < 8; w++) mx = fmaxf(mx, red[w]);
        __syncthreads();

        float lsum = 0.f;
        for (int i = tid; i < N_; i += 256) {
            float e = __expf(scores[i] - mx);
            scores[i] = e;
            lsum += e;
        }
#pragma unroll
        for (int off = 16; off; off >>= 1)
            lsum += __shfl_xor_sync(0xffffffffu, lsum, off);
        if (lane == 0) red[warp] = lsum;
        __syncthreads();
        float sum = 0.f;
#pragma unroll
        for (int w = 0; w < 8; w++) sum += red[w];
        const float inv = 1.0f / sum;

        float a0 = 0.f, a1 = 0.f;
        for (int j = warp; j < N_; j += 8) {
            const float p = scores[j];
            const float* vp = g_QKV + krow0 + (size_t)j * (3 * C_) + voff;
            a0 = fmaf(p, vp[lane],      a0);
            a1 = fmaf(p, vp[lane + 32], a1);
        }
        partA[warp * 64 + lane]      = a0;
        partA[warp * 64 + lane + 32] = a1;
        __syncthreads();

        if (warp == 0) {
            float t0 = 0.f, t1 = 0.f;
#pragma unroll
            for (int w = 0; w < 8; w++) {
                t0 += partA[w * 64 + lane];
                t1 += partA[w * 64 + lane + 32];
            }
            t0 *= inv; t1 *= inv;
            const size_t o = rowm * C_ + h * D_;
            const __nv_bfloat16 h0 = __float2bfloat16(t0);
            const __nv_bfloat16 h1 = __float2bfloat16(t1);
            g_Ohi[o + lane]      = h0;
            g_Olo[o + lane]      = __float2bfloat16(t0 - __bfloat162float(h0));
            g_Ohi[o + lane + 32] = h1;
            g_Olo[o + lane + 32] = __float2bfloat16(t1 - __bfloat162float(h1));
        }
    }
}

// ============================================================================
// launch
// ============================================================================
extern "C" void kernel_launch(void* const* d_in, const int* in_sizes, int n_in,
                              void* d_out, int out_size)
{
    const float* x     = (const float*)d_in[0];
    const float* Wqkv  = (const float*)d_in[1];
    const float* Wproj = (const float*)d_in[2];
    const float* bproj = (const float*)d_in[3];
    float* out = (float*)d_out;

    cudaFuncSetAttribute(hmma_gemm_kernel,
                         cudaFuncAttributeMaxDynamicSharedMemorySize, GEMM_SMEM);
    cudaFuncSetAttribute(attn_kernel,
                         cudaFuncAttributeMaxDynamicSharedMemorySize, ATT_SMEM);

    // 0) conversions
    {
        size_t total = (size_t)MPAD_ * K_;
        conv_x_kernel<<<(unsigned)((total + 255) / 256), 256>>>(x);
        __nv_bfloat16 *whi, *wlo, *phi, *plo;
        cudaGetSymbolAddress((void**)&whi, g_Whi);
        cudaGetSymbolAddress((void**)&wlo, g_Wlo);
        cudaGetSymbolAddress((void**)&phi, g_Phi);
        cudaGetSymbolAddress((void**)&plo, g_Plo);
        conv_wT_kernel<<<dim3(3 * C_ / 32, K_ / 32), 256>>>(Wqkv, whi, wlo, 3 * C_);
        conv_wT_kernel<<<dim3(C_ / 32, K_ / 32), 256>>>(Wproj, phi, plo, C_);
    }

    __nv_bfloat16 *xhi, *xlo, *whi, *wlo, *phi, *plo, *ohi, *olo;
    float* qkv;
    cudaGetSymbolAddress((void**)&xhi, g_xhi);
    cudaGetSymbolAddress((void**)&xlo, g_xlo);
    cudaGetSymbolAddress((void**)&whi, g_Whi);
    cudaGetSymbolAddress((void**)&wlo, g_Wlo);
    cudaGetSymbolAddress((void**)&phi, g_Phi);
    cudaGetSymbolAddress((void**)&plo, g_Plo);
    cudaGetSymbolAddress((void**)&ohi, g_Ohi);
    cudaGetSymbolAddress((void**)&olo, g_Olo);
    cudaGetSymbolAddress((void**)&qkv, g_QKV);

    // 1) QKV GEMM
    hmma_gemm_kernel<<<dim3(3 * C_ / 64, MT_), 256, GEMM_SMEM>>>(
        xhi, xlo, whi, wlo, nullptr, qkv, 3 * C_, M_);

    // 2) attention: 384 sliding CTAs + 384 CLS CTAs
    attn_kernel<<<2 * B_ * H_, 256, ATT_SMEM>>>();

    // 3) proj GEMM
    hmma_gemm_kernel<<<dim3(C_ / 64, MT_), 256, GEMM_SMEM>>>(
        ohi, olo, phi, plo, bproj, out, C_, M_);
}

// round 9
// speedup vs baseline: 1.1722x; 1.1722x over previous
#include <cuda_runtime.h>
#include <cuda_bf16.h>
#include <cstdint>
#include <math.h>

// ---------------- problem constants ----------------
#define B_    32
#define N_    577
#define C_    768
#define H_    12
#define D_    64
#define GRID_ 24
#define RAD_  3
#define K_    768
#define M_    (B_*N_)      // 18464
#define MT_   145          // ceil(M/128)
#define MPAD_ (MT_*128)    // 18560

// ---------------- device-global scratch ----------------
__device__ __nv_bfloat16 g_xhi[MPAD_*K_];
__device__ __nv_bfloat16 g_xlo[MPAD_*K_];
__device__ __nv_bfloat16 g_Whi[3*C_*K_];   // Wqkv^T  [2304,768]
__device__ __nv_bfloat16 g_Wlo[3*C_*K_];
__device__ __nv_bfloat16 g_Phi[C_*K_];     // Wproj^T [768,768]
__device__ __nv_bfloat16 g_Plo[C_*K_];
__device__ float         g_QKV[(size_t)M_*3*C_];      // [m, 2304]
__device__ __nv_bfloat16 g_Ohi[MPAD_*C_];
__device__ __nv_bfloat16 g_Olo[MPAD_*C_];

// ---------------- PTX helpers ----------------
__device__ __forceinline__ uint32_t smem_u32(const void* p) {
    uint32_t a;
    asm("{ .reg .u64 t; cvta.to.shared.u64 t, %1; cvt.u32.u64 %0, t; }" : "=r"(a) : "l"(p));
    return a;
}
__device__ __forceinline__ void cp_async16(uint32_t dst, const void* src) {
    asm volatile("cp.async.cg.shared.global [%0], [%1], 16;" :: "r"(dst), "l"(src));
}
__device__ __forceinline__ void cp_commit() {
    asm volatile("cp.async.commit_group;");
}
template <int NN>
__device__ __forceinline__ void cp_wait() {
    asm volatile("cp.async.wait_group %0;" :: "n"(NN));
}
__device__ __forceinline__ void ldmatrix_x4(uint32_t& r0, uint32_t& r1,
                                            uint32_t& r2, uint32_t& r3, uint32_t addr) {
    asm volatile("ldmatrix.sync.aligned.m8n8.x4.shared.b16 {%0,%1,%2,%3}, [%4];"
                 : "=r"(r0), "=r"(r1), "=r"(r2), "=r"(r3) : "r"(addr));
}
__device__ __forceinline__ void mma_bf16(float* c, const uint32_t* a,
                                         uint32_t b0, uint32_t b1) {
    asm volatile(
        "mma.sync.aligned.m16n8k16.row.col.f32.bf16.bf16.f32 "
        "{%0,%1,%2,%3}, {%4,%5,%6,%7}, {%8,%9}, {%0,%1,%2,%3};"
        : "+f"(c[0]), "+f"(c[1]), "+f"(c[2]), "+f"(c[3])
        : "r"(a[0]), "r"(a[1]), "r"(a[2]), "r"(a[3]), "r"(b0), "r"(b1));
}

// ============================================================================
// conversion kernels
// ============================================================================
__global__ void conv_x_kernel(const float* __restrict__ x) {
    size_t idx = (size_t)blockIdx.x * 256 + threadIdx.x;
    if (idx >= (size_t)MPAD_ * K_) return;
    size_t m = idx / K_;
    if (m < M_) {
        float a = x[idx];
        __nv_bfloat16 hi = __float2bfloat16(a);
        __nv_bfloat16 lo = __float2bfloat16(a - __bfloat162float(hi));
        g_xhi[idx] = hi;
        g_xlo[idx] = lo;
    } else {
        g_xhi[idx] = __float2bfloat16(0.f);
        g_xlo[idx] = __float2bfloat16(0.f);
        g_Ohi[idx] = __float2bfloat16(0.f);
        g_Olo[idx] = __float2bfloat16(0.f);
    }
}

__global__ void conv_wT_kernel(const float* __restrict__ W,
                               __nv_bfloat16* __restrict__ Thi,
                               __nv_bfloat16* __restrict__ Tlo, int Ncols) {
    __shared__ float t[32][33];
    const int kc = blockIdx.y * 32;
    const int nc = blockIdx.x * 32;
    const int tx = threadIdx.x & 31;
    const int ty = threadIdx.x >> 5;
    for (int i = ty; i < 32; i += 8)
        t[i][tx] = W[(size_t)(kc + i) * Ncols + nc + tx];
    __syncthreads();
    for (int i = ty; i < 32; i += 8) {
        float a = t[tx][i];
        __nv_bfloat16 hi = __float2bfloat16(a);
        __nv_bfloat16 lo = __float2bfloat16(a - __bfloat162float(hi));
        size_t o = (size_t)(nc + i) * K_ + kc + tx;
        Thi[o] = hi;
        Tlo[o] = lo;
    }
}

// ============================================================================
// split-bf16 HMMA GEMM: 128x64x64 tiles, 2-stage cp.async, 2 CTAs/SM
// ============================================================================
#define NCHUNK   (K_/64)          // 12
#define A_B      (128*128)
#define B_B      (64*128)
#define STAGE_B  (2*A_B + 2*B_B)  // 48KB
#define GEMM_SMEM (2*STAGE_B)     // 96KB

__global__ __launch_bounds__(256, 2)
void hmma_gemm_kernel(const __nv_bfloat16* __restrict__ Ahi,
                      const __nv_bfloat16* __restrict__ Alo,
                      const __nv_bfloat16* __restrict__ Bhi,
                      const __nv_bfloat16* __restrict__ Blo,
                      const float* __restrict__ bias,
                      float* __restrict__ Cout,
                      int Ncols, int Mrows)
{
    extern __shared__ unsigned char smem[];
    const uint32_t s_base = smem_u32(smem);

    const int tid   = threadIdx.x;
    const int wid   = tid >> 5;
    const int lane  = tid & 31;
    const int m0    = blockIdx.y * 128;
    const int n0    = blockIdx.x * 64;
    const int wm    = (wid >> 1) * 32;
    const int wn    = (wid & 1) * 32;

    const int lr = tid >> 3;
    const int lc = tid & 7;
    auto load_stage = [&](int st, int kc) {
        const uint32_t sb = s_base + st * STAGE_B;
        const int k0 = kc * 64 + lc * 8;
#pragma unroll
        for (int i = 0; i < 4; i++) {
            const int row = lr + i * 32;
            const uint32_t so = row * 128 + ((lc ^ (row & 7)) << 4);
            const size_t ga = (size_t)(m0 + row) * K_ + k0;
            cp_async16(sb + so,        Ahi + ga);
            cp_async16(sb + A_B + so,  Alo + ga);
        }
#pragma unroll
        for (int i = 0; i < 2; i++) {
            const int row = lr + i * 32;
            const uint32_t so = row * 128 + ((lc ^ (row & 7)) << 4);
            const size_t gb = (size_t)(n0 + row) * K_ + k0;
            cp_async16(sb + 2*A_B + so,        Bhi + gb);
            cp_async16(sb + 2*A_B + B_B + so,  Blo + gb);
        }
    };

    float acc[2][4][4];
#pragma unroll
    for (int i = 0; i < 2; i++)
#pragma unroll
        for (int j = 0; j < 4; j++)
#pragma unroll
            for (int v = 0; v < 4; v++) acc[i][j][v] = 0.f;

    load_stage(0, 0); cp_commit();

    const int a_row = (lane & 15);
    const int a_chi = (lane >> 4);
    const int b_row = (lane & 7) + ((lane >> 4) << 3);
    const int b_chi = (lane >> 3) & 1;

    for (int kc = 0; kc < NCHUNK; kc++) {
        if (kc + 1 < NCHUNK) {
            load_stage((kc + 1) & 1, kc + 1);
            cp_commit();
            cp_wait<1>();
        } else {
            cp_wait<0>();
        }
        __syncthreads();

        const uint32_t sb   = s_base + (kc & 1) * STAGE_B;
        const uint32_t sAhi = sb;
        const uint32_t sAlo = sb + A_B;
        const uint32_t sBhi = sb + 2*A_B;
        const uint32_t sBlo = sb + 2*A_B + B_B;

#pragma unroll
        for (int s = 0; s < 4; s++) {
            uint32_t fah[2][4], fal[2][4];
#pragma unroll
            for (int mi = 0; mi < 2; mi++) {
                const int row = wm + mi * 16 + a_row;
                const int ch  = (2 * s + a_chi) ^ (row & 7);
                const uint32_t off = row * 128 + (ch << 4);
                ldmatrix_x4(fah[mi][0], fah[mi][1], fah[mi][2], fah[mi][3], sAhi + off);
                ldmatrix_x4(fal[mi][0], fal[mi][1], fal[mi][2], fal[mi][3], sAlo + off);
            }
            uint32_t fbh[2][4], fbl[2][4];
#pragma unroll
            for (int ng = 0; ng < 2; ng++) {
                const int row = wn + ng * 16 + b_row;
                const int ch  = (2 * s + b_chi) ^ (row & 7);
                const uint32_t off = row * 128 + (ch << 4);
                ldmatrix_x4(fbh[ng][0], fbh[ng][1], fbh[ng][2], fbh[ng][3], sBhi + off);
                ldmatrix_x4(fbl[ng][0], fbl[ng][1], fbl[ng][2], fbl[ng][3], sBlo + off);
            }
#pragma unroll
            for (int mi = 0; mi < 2; mi++) {
#pragma unroll
                for (int ng = 0; ng < 2; ng++) {
#pragma unroll
                    for (int hh = 0; hh < 2; hh++) {
                        float* c = acc[mi][ng * 2 + hh];
                        const uint32_t bh0 = fbh[ng][hh * 2], bh1 = fbh[ng][hh * 2 + 1];
                        const uint32_t bl0 = fbl[ng][hh * 2], bl1 = fbl[ng][hh * 2 + 1];
                        mma_bf16(c, fah[mi], bh0, bh1);
                        mma_bf16(c, fah[mi], bl0, bl1);
                        mma_bf16(c, fal[mi], bh0, bh1);
                    }
                }
            }
        }
        __syncthreads();
    }

#pragma unroll
    for (int ni = 0; ni < 4; ni++) {
        const int col = n0 + wn + ni * 8 + (lane & 3) * 2;
        const float bx = bias ? bias[col]     : 0.f;
        const float by = bias ? bias[col + 1] : 0.f;
#pragma unroll
        for (int mi = 0; mi < 2; mi++) {
            const int r0 = m0 + wm + mi * 16 + (lane >> 2);
            if (r0 < Mrows) {
                float2 v = make_float2(acc[mi][ni][0] + bx, acc[mi][ni][1] + by);
                *(float2*)(Cout + (size_t)r0 * Ncols + col) = v;
            }
            const int r1 = r0 + 8;
            if (r1 < Mrows) {
                float2 v = make_float2(acc[mi][ni][2] + bx, acc[mi][ni][3] + by);
                *(float2*)(Cout + (size_t)r1 * Ncols + col) = v;
            }
        }
    }
}

// ============================================================================
// attention: one CTA per (b, h, 3-row group) + CLS CTAs
//   band = rows [3g-3, 3g+5] clamped (<=9 rows => <=217 keys incl CLS)
//   two-pass: K band -> probs for 72 queries -> V band overwrites K -> AV
//   AV uses direct nested addressing (no slot indirection)
// ============================================================================
#define NRG       8                   // row groups per head (24/3)
#define NLOCALBLK (B_*H_*NRG)         // 3072
#define MAXNK     217                 // 1 + 9*24
#define KSTR      68
#define SKV_F     (MAXNK*KSTR)        // 14756 floats
#define SQ_F      (72*64)             // 4608
#define SP_F      (72*64)             // 4608
#define ATT_SMEM  ((SKV_F + SQ_F + SP_F)*4)   // 95,888 B

__global__ __launch_bounds__(256, 2)
void attn_kernel()
{
    extern __shared__ float sm[];

    const int tid  = threadIdx.x;
    const int lane = tid & 31;
    const int warp = tid >> 5;
    const int blk  = blockIdx.x;

    if (blk < NLOCALBLK) {
        // ---------------- 3-row-group local CTA ----------------
        float* sKV   = sm;                  // [217][68] K band, then V band
        float* sQ    = sm + SKV_F;          // [72][64]
        float* sProb = sm + SKV_F + SQ_F;   // [72][64]

        const int rg = blk % NRG;
        const int h  = (blk / NRG) % H_;
        const int b  = blk / (NRG * H_);
        const int rbase = rg * 3;

        const int br0 = (rbase - RAD_ < 0) ? 0 : rbase - RAD_;
        const int br1 = (rbase + 2 + RAD_ > GRID_ - 1) ? GRID_ - 1 : rbase + 2 + RAD_;
        const int nrows = br1 - br0 + 1;
        const int nk = 1 + nrows * GRID_;

        const size_t base = (size_t)b * N_ * (3 * C_);
        const int qoff = h * D_;
        const int koff = C_ + h * D_;
        const int voff = 2 * C_ + h * D_;

        // ---- phase 0: queries (72 rows) ----
        for (int i = tid; i < 72 * 16; i += 256) {
            const int qi   = i >> 4;
            const int part = i & 15;
            const int n = 1 + (rbase + qi / GRID_) * GRID_ + qi % GRID_;
            const float4 qv = *(const float4*)(g_QKV + base + (size_t)n * (3 * C_) + qoff + part * 4);
            *(float4*)(sQ + qi * 64 + part * 4) = qv;
        }
        // ---- phase 1: K band ----
        for (int i = tid; i < nk * 16; i += 256) {
            const int slot = i >> 4;
            const int part = i & 15;
            const int gkey = (slot == 0) ? 0
                           : (1 + (br0 + (slot - 1) / GRID_) * GRID_ + (slot - 1) % GRID_);
            const float4 kv = *(const float4*)(g_QKV + base + (size_t)gkey * (3 * C_) + koff + part * 4);
            *(float4*)(sKV + slot * KSTR + part * 4) = kv;
        }
        __syncthreads();

        // ---- probs for 72 queries (8 warps x 9) ----
        for (int qi = warp; qi < 72; qi += 8) {
            const int lr = qi / GRID_;
            const int c  = qi % GRID_;
            const int r  = rbase + lr;

            const int r0 = (r - RAD_ < 0) ? 0 : r - RAD_;
            const int r1 = (r + RAD_ > GRID_ - 1) ? GRID_ - 1 : r + RAD_;
            const int span = r1 - r0 + 1;
            const int c0 = (c - RAD_ < 0) ? 0 : c - RAD_;
            const int c1 = (c + RAD_ > GRID_ - 1) ? GRID_ - 1 : c + RAD_;
            const int cw = c1 - c0 + 1;
            const int cnt = 1 + span * cw;

            int slot0 = 0, slot1 = 0;
            if (lane > 0 && lane < cnt) {
                const int j = lane - 1;
                slot0 = 1 + (r0 - br0 + j / cw) * GRID_ + (c0 + j % cw);
            }
            if (lane + 32 < cnt) {
                const int j = lane + 31;
                slot1 = 1 + (r0 - br0 + j / cw) * GRID_ + (c0 + j % cw);
            }
            const float4* q4  = (const float4*)(sQ + qi * 64);
            const float4* kr0 = (const float4*)(sKV + slot0 * KSTR);
            const float4* kr1 = (const float4*)(sKV + slot1 * KSTR);
            float acc0 = 0.f, acc1 = 0.f;
#pragma unroll
            for (int i = 0; i < 16; i++) {
                const float4 qv = q4[i];
                const float4 k0 = kr0[i];
                const float4 k1 = kr1[i];
                acc0 += qv.x * k0.x + qv.y * k0.y + qv.z * k0.z + qv.w * k0.w;
                acc1 += qv.x * k1.x + qv.y * k1.y + qv.z * k1.z + qv.w * k1.w;
            }
            float s0 = (lane < cnt)      ? acc0 * 0.125f : -1e30f;
            float s1 = (lane + 32 < cnt) ? acc1 * 0.125f : -1e30f;

            float mx = fmaxf(s0, s1);
#pragma unroll
            for (int off = 16; off; off >>= 1)
                mx = fmaxf(mx, __shfl_xor_sync(0xffffffffu, mx, off));
            const float e0 = __expf(s0 - mx);
            const float e1 = __expf(s1 - mx);
            float sum = e0 + e1;
#pragma unroll
            for (int off = 16; off; off >>= 1)
                sum += __shfl_xor_sync(0xffffffffu, sum, off);
            const float inv = 1.0f / sum;

            sProb[qi * 64 + lane]      = e0 * inv;
            sProb[qi * 64 + lane + 32] = e1 * inv;
        }
        __syncthreads();

        // ---- phase 2: V band overwrites K ----
        for (int i = tid; i < nk * 16; i += 256) {
            const int slot = i >> 4;
            const int part = i & 15;
            const int gkey = (slot == 0) ? 0
                           : (1 + (br0 + (slot - 1) / GRID_) * GRID_ + (slot - 1) % GRID_);
            const float4 vv = *(const float4*)(g_QKV + base + (size_t)gkey * (3 * C_) + voff + part * 4);
            *(float4*)(sKV + slot * KSTR + part * 4) = vv;
        }
        __syncthreads();

        // ---- AV: direct nested addressing ----
        for (int qi = warp; qi < 72; qi += 8) {
            const int lr = qi / GRID_;
            const int c  = qi % GRID_;
            const int r  = rbase + lr;

            const int r0 = (r - RAD_ < 0) ? 0 : r - RAD_;
            const int r1 = (r + RAD_ > GRID_ - 1) ? GRID_ - 1 : r + RAD_;
            const int c0 = (c - RAD_ < 0) ? 0 : c - RAD_;
            const int c1 = (c + RAD_ > GRID_ - 1) ? GRID_ - 1 : c + RAD_;

            const float* wp = sProb + qi * 64;
            float a0, a1;
            {   // CLS key (slot 0)
                const float p = wp[0];
                const float2 v = *(const float2*)(sKV + 2 * lane);
                a0 = p * v.x;
                a1 = p * v.y;
            }
            int idx = 1;
            for (int rr = r0; rr <= r1; rr++) {
                const int rowb = 1 + (rr - br0) * GRID_;
#pragma unroll 4
                for (int cc = c0; cc <= c1; cc++) {
                    const float p = wp[idx++];
                    const float2 v = *(const float2*)(sKV + (rowb + cc) * KSTR + 2 * lane);
                    a0 = fmaf(p, v.x, a0);
                    a1 = fmaf(p, v.y, a1);
                }
            }

            const int n = 1 + r * GRID_ + c;
            const size_t o = ((size_t)b * N_ + n) * C_ + h * D_ + 2 * lane;
            const __nv_bfloat16 h0 = __float2bfloat16(a0);
            const __nv_bfloat16 h1 = __float2bfloat16(a1);
            __nv_bfloat162 hp; hp.x = h0; hp.y = h1;
            __nv_bfloat162 lp;
            lp.x = __float2bfloat16(a0 - __bfloat162float(h0));
            lp.y = __float2bfloat16(a1 - __bfloat162float(h1));
            *(__nv_bfloat162*)(g_Ohi + o) = hp;
            *(__nv_bfloat162*)(g_Olo + o) = lp;
        }
    } else {
        // ---------------- CLS CTA ----------------
        float* scores = sm;                 // [577] (+pad)
        float* partA  = sm + 640;           // [8][64]
        float* red    = sm + 640 + 8 * 64;  // [8]

        const int w2 = blk - NLOCALBLK;
        const int b  = w2 / H_;
        const int h  = w2 % H_;

        const size_t rowm = (size_t)b * N_;   // n = 0
        const float* qp = g_QKV + rowm * (3 * C_) + h * D_;
        const float q0 = qp[lane];
        const float q1 = qp[lane + 32];

        const size_t krow0 = (size_t)b * N_ * (3 * C_);
        const int koff = C_ + h * D_;
        const int voff = 2 * C_ + h * D_;

        for (int j = warp; j < N_; j += 8) {
            const float* kp = g_QKV + krow0 + (size_t)j * (3 * C_) + koff;
            float s = q0 * kp[lane] + q1 * kp[lane + 32];
#pragma unroll
            for (int off = 16; off; off >>= 1)
                s += __shfl_xor_sync(0xffffffffu, s, off);
            if (lane == 0) scores[j] = s * 0.125f;
        }
        __syncthreads();

        float mx = -1e30f;
        for (int i = tid; i < N_; i += 256) mx = fmaxf(mx, scores[i]);
#pragma unroll
        for (int off = 16; off; off >>= 1)
            mx = fmaxf(mx, __shfl_xor_sync(0xffffffffu, mx, off));
        if (lane == 0) red[warp] = mx;
        __syncthreads();
        mx = red[0];
#pragma unroll
        for (int w = 1; w < 8; w++) mx = fmaxf(mx, red[w]);
        __syncthreads();

        float lsum = 0.f;
        for (int i = tid; i < N_; i += 256) {
            float e = __expf(scores[i] - mx);
            scores[i] = e;
            lsum += e;
        }
#pragma unroll
        for (int off = 16; off; off >>= 1)
            lsum += __shfl_xor_sync(0xffffffffu, lsum, off);
        if (lane == 0) red[warp] = lsum;
        __syncthreads();
        float sum = 0.f;
#pragma unroll
        for (int w = 0; w < 8; w++) sum += red[w];
        const float inv = 1.0f / sum;

        float a0 = 0.f, a1 = 0.f;
        for (int j = warp; j < N_; j += 8) {
            const float p = scores[j];
            const float* vp = g_QKV + krow0 + (size_t)j * (3 * C_) + voff;
            a0 = fmaf(p, vp[lane],      a0);
            a1 = fmaf(p, vp[lane + 32], a1);
        }
        partA[warp * 64 + lane]      = a0;
        partA[warp * 64 + lane + 32] = a1;
        __syncthreads();

        if (warp == 0) {
            float t0 = 0.f, t1 = 0.f;
#pragma unroll
            for (int w = 0; w < 8; w++) {
                t0 += partA[w * 64 + lane];
                t1 += partA[w * 64 + lane + 32];
            }
            t0 *= inv; t1 *= inv;
            const size_t o = rowm * C_ + h * D_;
            const __nv_bfloat16 h0 = __float2bfloat16(t0);
            const __nv_bfloat16 h1 = __float2bfloat16(t1);
            g_Ohi[o + lane]      = h0;
            g_Olo[o + lane]      = __float2bfloat16(t0 - __bfloat162float(h0));
            g_Ohi[o + lane + 32] = h1;
            g_Olo[o + lane + 32] = __float2bfloat16(t1 - __bfloat162float(h1));
        }
    }
}

// ============================================================================
// launch
// ============================================================================
extern "C" void kernel_launch(void* const* d_in, const int* in_sizes, int n_in,
                              void* d_out, int out_size)
{
    const float* x     = (const float*)d_in[0];
    const float* Wqkv  = (const float*)d_in[1];
    const float* Wproj = (const float*)d_in[2];
    const float* bproj = (const float*)d_in[3];
    float* out = (float*)d_out;

    cudaFuncSetAttribute(hmma_gemm_kernel,
                         cudaFuncAttributeMaxDynamicSharedMemorySize, GEMM_SMEM);
    cudaFuncSetAttribute(attn_kernel,
                         cudaFuncAttributeMaxDynamicSharedMemorySize, ATT_SMEM);

    // 0) conversions
    {
        size_t total = (size_t)MPAD_ * K_;
        conv_x_kernel<<<(unsigned)((total + 255) / 256), 256>>>(x);
        __nv_bfloat16 *whi, *wlo, *phi, *plo;
        cudaGetSymbolAddress((void**)&whi, g_Whi);
        cudaGetSymbolAddress((void**)&wlo, g_Wlo);
        cudaGetSymbolAddress((void**)&phi, g_Phi);
        cudaGetSymbolAddress((void**)&plo, g_Plo);
        conv_wT_kernel<<<dim3(3 * C_ / 32, K_ / 32), 256>>>(Wqkv, whi, wlo, 3 * C_);
        conv_wT_kernel<<<dim3(C_ / 32, K_ / 32), 256>>>(Wproj, phi, plo, C_);
    }

    __nv_bfloat16 *xhi, *xlo, *whi, *wlo, *phi, *plo, *ohi, *olo;
    float* qkv;
    cudaGetSymbolAddress((void**)&xhi, g_xhi);
    cudaGetSymbolAddress((void**)&xlo, g_xlo);
    cudaGetSymbolAddress((void**)&whi, g_Whi);
    cudaGetSymbolAddress((void**)&wlo, g_Wlo);
    cudaGetSymbolAddress((void**)&phi, g_Phi);
    cudaGetSymbolAddress((void**)&plo, g_Plo);
    cudaGetSymbolAddress((void**)&ohi, g_Ohi);
    cudaGetSymbolAddress((void**)&olo, g_Olo);
    cudaGetSymbolAddress((void**)&qkv, g_QKV);

    // 1) QKV GEMM
    hmma_gemm_kernel<<<dim3(3 * C_ / 64, MT_), 256, GEMM_SMEM>>>(
        xhi, xlo, whi, wlo, nullptr, qkv, 3 * C_, M_);

    // 2) attention: 3072 local CTAs + 384 CLS CTAs
    attn_kernel<<<NLOCALBLK + B_ * H_, 256, ATT_SMEM>>>();

    // 3) proj GEMM
    hmma_gemm_kernel<<<dim3(C_ / 64, MT_), 256, GEMM_SMEM>>>(
        ohi, olo, phi, plo, bproj, out, C_, M_);
}

// round 10
// speedup vs baseline: 1.4513x; 1.2381x over previous
#include <cuda_runtime.h>
#include <cuda_fp16.h>
#include <cstdint>
#include <math.h>

// ---------------- problem constants ----------------
#define B_    32
#define N_    577
#define C_    768
#define H_    12
#define D_    64
#define GRID_ 24
#define RAD_  3
#define K_    768
#define M_    (B_*N_)      // 18464
#define MT_   145          // ceil(M/128)
#define MPAD_ (MT_*128)    // 18560

// ---------------- device-global scratch ----------------
__device__ __half  g_xhi[MPAD_*K_];
__device__ __half  g_xlo[MPAD_*K_];
__device__ __half  g_Whi[3*C_*K_];   // Wqkv^T  [2304,768] fp16
__device__ __half  g_Phi[C_*K_];     // Wproj^T [768,768]  fp16
__device__ float   g_QKV[(size_t)M_*3*C_];      // [m, 2304]
__device__ __half  g_Ohi[MPAD_*C_];
__device__ __half  g_Olo[MPAD_*C_];

// ---------------- PTX helpers ----------------
__device__ __forceinline__ uint32_t smem_u32(const void* p) {
    uint32_t a;
    asm("{ .reg .u64 t; cvta.to.shared.u64 t, %1; cvt.u32.u64 %0, t; }" : "=r"(a) : "l"(p));
    return a;
}
__device__ __forceinline__ void cp_async16(uint32_t dst, const void* src) {
    asm volatile("cp.async.cg.shared.global [%0], [%1], 16;" :: "r"(dst), "l"(src));
}
__device__ __forceinline__ void cp_commit() {
    asm volatile("cp.async.commit_group;");
}
template <int NN>
__device__ __forceinline__ void cp_wait() {
    asm volatile("cp.async.wait_group %0;" :: "n"(NN));
}
__device__ __forceinline__ void ldmatrix_x4(uint32_t& r0, uint32_t& r1,
                                            uint32_t& r2, uint32_t& r3, uint32_t addr) {
    asm volatile("ldmatrix.sync.aligned.m8n8.x4.shared.b16 {%0,%1,%2,%3}, [%4];"
                 : "=r"(r0), "=r"(r1), "=r"(r2), "=r"(r3) : "r"(addr));
}
__device__ __forceinline__ void mma_fp16(float* c, const uint32_t* a,
                                         uint32_t b0, uint32_t b1) {
    asm volatile(
        "mma.sync.aligned.m16n8k16.row.col.f32.f16.f16.f32 "
        "{%0,%1,%2,%3}, {%4,%5,%6,%7}, {%8,%9}, {%0,%1,%2,%3};"
        : "+f"(c[0]), "+f"(c[1]), "+f"(c[2]), "+f"(c[3])
        : "r"(a[0]), "r"(a[1]), "r"(a[2]), "r"(a[3]), "r"(b0), "r"(b1));
}

// ============================================================================
// conversion kernels
// ============================================================================
__global__ void conv_x_kernel(const float* __restrict__ x) {
    size_t idx = (size_t)blockIdx.x * 256 + threadIdx.x;
    if (idx >= (size_t)MPAD_ * K_) return;
    size_t m = idx / K_;
    if (m < M_) {
        float a = x[idx];
        __half hi = __float2half(a);
        __half lo = __float2half(a - __half2float(hi));
        g_xhi[idx] = hi;
        g_xlo[idx] = lo;
    } else {
        g_xhi[idx] = __float2half(0.f);
        g_xlo[idx] = __float2half(0.f);
        g_Ohi[idx] = __float2half(0.f);   // same index space [MPAD*768]
        g_Olo[idx] = __float2half(0.f);
    }
}

// transpose-convert: W [K_, Ncols] fp32 -> T [Ncols, K_] fp16 (hi only)
__global__ void conv_wT_kernel(const float* __restrict__ W,
                               __half* __restrict__ Thi, int Ncols) {
    __shared__ float t[32][33];
    const int kc = blockIdx.y * 32;
    const int nc = blockIdx.x * 32;
    const int tx = threadIdx.x & 31;
    const int ty = threadIdx.x >> 5;
    for (int i = ty; i < 32; i += 8)
        t[i][tx] = W[(size_t)(kc + i) * Ncols + nc + tx];
    __syncthreads();
    for (int i = ty; i < 32; i += 8) {
        size_t o = (size_t)(nc + i) * K_ + kc + tx;
        Thi[o] = __float2half(t[tx][i]);
    }
}

// ============================================================================
// fp16 2-term HMMA GEMM: C = (Ahi+Alo) @ Bhi^T (+bias)
// 128x64x64 tiles, 2-stage cp.async, 2 CTAs/SM, 8 warps (4x2), warp tile 32x32
// ============================================================================
#define NCHUNK   (K_/64)          // 12
#define A_B      (128*128)        // 16KB per A tile (hi or lo)
#define B_B      (64*128)         // 8KB  B tile
#define STAGE_B  (2*A_B + B_B)    // 40KB per stage
#define GEMM_SMEM (2*STAGE_B)     // 80KB

__global__ __launch_bounds__(256, 2)
void hmma_gemm_kernel(const __half* __restrict__ Ahi,
                      const __half* __restrict__ Alo,
                      const __half* __restrict__ Bh,
                      const float* __restrict__ bias,
                      float* __restrict__ Cout,
                      int Ncols, int Mrows)
{
    extern __shared__ unsigned char smem[];
    const uint32_t s_base = smem_u32(smem);

    const int tid   = threadIdx.x;
    const int wid   = tid >> 5;
    const int lane  = tid & 31;
    const int m0    = blockIdx.y * 128;
    const int n0    = blockIdx.x * 64;
    const int wm    = (wid >> 1) * 32;
    const int wn    = (wid & 1) * 32;

    const int lr = tid >> 3;
    const int lc = tid & 7;
    auto load_stage = [&](int st, int kc) {
        const uint32_t sb = s_base + st * STAGE_B;
        const int k0 = kc * 64 + lc * 8;
#pragma unroll
        for (int i = 0; i < 4; i++) {
            const int row = lr + i * 32;
            const uint32_t so = row * 128 + ((lc ^ (row & 7)) << 4);
            const size_t ga = (size_t)(m0 + row) * K_ + k0;
            cp_async16(sb + so,        Ahi + ga);
            cp_async16(sb + A_B + so,  Alo + ga);
        }
#pragma unroll
        for (int i = 0; i < 2; i++) {
            const int row = lr + i * 32;
            const uint32_t so = row * 128 + ((lc ^ (row & 7)) << 4);
            const size_t gb = (size_t)(n0 + row) * K_ + k0;
            cp_async16(sb + 2*A_B + so, Bh + gb);
        }
    };

    float acc[2][4][4];
#pragma unroll
    for (int i = 0; i < 2; i++)
#pragma unroll
        for (int j = 0; j < 4; j++)
#pragma unroll
            for (int v = 0; v < 4; v++) acc[i][j][v] = 0.f;

    load_stage(0, 0); cp_commit();

    const int a_row = (lane & 15);
    const int a_chi = (lane >> 4);
    const int b_row = (lane & 7) + ((lane >> 4) << 3);
    const int b_chi = (lane >> 3) & 1;

    for (int kc = 0; kc < NCHUNK; kc++) {
        if (kc + 1 < NCHUNK) {
            load_stage((kc + 1) & 1, kc + 1);
            cp_commit();
            cp_wait<1>();
        } else {
            cp_wait<0>();
        }
        __syncthreads();

        const uint32_t sb   = s_base + (kc & 1) * STAGE_B;
        const uint32_t sAhi = sb;
        const uint32_t sAlo = sb + A_B;
        const uint32_t sBh  = sb + 2*A_B;

#pragma unroll
        for (int s = 0; s < 4; s++) {
            uint32_t fah[2][4], fal[2][4];
#pragma unroll
            for (int mi = 0; mi < 2; mi++) {
                const int row = wm + mi * 16 + a_row;
                const int ch  = (2 * s + a_chi) ^ (row & 7);
                const uint32_t off = row * 128 + (ch << 4);
                ldmatrix_x4(fah[mi][0], fah[mi][1], fah[mi][2], fah[mi][3], sAhi + off);
                ldmatrix_x4(fal[mi][0], fal[mi][1], fal[mi][2], fal[mi][3], sAlo + off);
            }
            uint32_t fbh[2][4];
#pragma unroll
            for (int ng = 0; ng < 2; ng++) {
                const int row = wn + ng * 16 + b_row;
                const int ch  = (2 * s + b_chi) ^ (row & 7);
                const uint32_t off = row * 128 + (ch << 4);
                ldmatrix_x4(fbh[ng][0], fbh[ng][1], fbh[ng][2], fbh[ng][3], sBh + off);
            }
#pragma unroll
            for (int mi = 0; mi < 2; mi++) {
#pragma unroll
                for (int ng = 0; ng < 2; ng++) {
#pragma unroll
                    for (int hh = 0; hh < 2; hh++) {
                        float* c = acc[mi][ng * 2 + hh];
                        const uint32_t b0 = fbh[ng][hh * 2], b1 = fbh[ng][hh * 2 + 1];
                        mma_fp16(c, fah[mi], b0, b1);
                        mma_fp16(c, fal[mi], b0, b1);
                    }
                }
            }
        }
        __syncthreads();
    }

#pragma unroll
    for (int ni = 0; ni < 4; ni++) {
        const int col = n0 + wn + ni * 8 + (lane & 3) * 2;
        const float bx = bias ? bias[col]     : 0.f;
        const float by = bias ? bias[col + 1] : 0.f;
#pragma unroll
        for (int mi = 0; mi < 2; mi++) {
            const int r0 = m0 + wm + mi * 16 + (lane >> 2);
            if (r0 < Mrows) {
                float2 v = make_float2(acc[mi][ni][0] + bx, acc[mi][ni][1] + by);
                *(float2*)(Cout + (size_t)r0 * Ncols + col) = v;
            }
            const int r1 = r0 + 8;
            if (r1 < Mrows) {
                float2 v = make_float2(acc[mi][ni][2] + bx, acc[mi][ni][3] + by);
                *(float2*)(Cout + (size_t)r1 * Ncols + col) = v;
            }
        }
    }
}

// ============================================================================
// merged attention kernel (R7 structure — best measured variant)
//   blk <  B*H*GRID  : local-row CTA (two-pass K/V smem reuse, 8 warps x 3 q)
//   blk >= B*H*GRID  : CLS CTA for (b,h)
// ============================================================================
#define MAXNK     169
#define KSTR      68
#define NLOCALBLK (B_*H_*GRID_)      // 9216
#define SQ_F      (24*64)
#define SKV_F     (MAXNK*KSTR)
#define ATT_SMEM  ((SQ_F + SKV_F + 24*64*2) * 4)   // ~64KB

__global__ __launch_bounds__(256, 3)
void attn_kernel()
{
    extern __shared__ float sm[];

    const int tid  = threadIdx.x;
    const int lane = tid & 31;
    const int warp = tid >> 5;
    const int blk  = blockIdx.x;

    if (blk < NLOCALBLK) {
        float*  sQ   = sm;                           // [24][64]
        float*  sKV  = sm + SQ_F;                    // [169][68]
        float2* pack = (float2*)(sm + SQ_F + SKV_F); // [24][64] (prob, slot)

        const int r = blk % GRID_;
        const int h = (blk / GRID_) % H_;
        const int b = blk / (GRID_ * H_);

        const int r0   = (r - RAD_ < 0) ? 0 : r - RAD_;
        const int r1   = (r + RAD_ > GRID_ - 1) ? GRID_ - 1 : r + RAD_;
        const int span = r1 - r0 + 1;
        const int nk   = span * GRID_ + 1;

        const size_t krow0 = (size_t)b * N_ * (3 * C_);
        const int koff = C_ + h * D_;
        const int voff = 2 * C_ + h * D_;
        const size_t qbase = ((size_t)b * N_ + 1 + r * GRID_) * (3 * C_) + h * D_;

        // ---- phase 0: queries ----
        for (int i = tid; i < 24 * 16; i += 256) {
            const int c    = i >> 4;
            const int part = i & 15;
            const float4 qv = *(const float4*)(g_QKV + qbase + (size_t)c * (3 * C_) + part * 4);
            *(float4*)(sQ + c * 64 + part * 4) = qv;
        }
        // ---- phase 1: K band ----
        for (int i = tid; i < nk * 16; i += 256) {
            const int slot = i >> 4;
            const int part = i & 15;
            const int gkey = (slot == 0) ? 0
                           : (1 + (r0 + (slot - 1) / GRID_) * GRID_ + (slot - 1) % GRID_);
            const float4 kv = *(const float4*)(g_QKV + krow0 + (size_t)gkey * (3 * C_) + koff + part * 4);
            *(float4*)(sKV + slot * KSTR + part * 4) = kv;
        }
        __syncthreads();

        for (int c = warp; c < GRID_; c += 8) {
            const int c0 = (c - RAD_ < 0) ? 0 : c - RAD_;
            const int c1 = (c + RAD_ > GRID_ - 1) ? GRID_ - 1 : c + RAD_;
            const int cw = c1 - c0 + 1;
            const int cnt = 1 + span * cw;

            int slot0 = 0, slot1 = 0;
            if (lane > 0 && lane < cnt) {
                const int j = lane - 1;
                slot0 = 1 + (j / cw) * GRID_ + (c0 + j % cw);
            }
            if (lane + 32 < cnt) {
                const int j = lane + 31;
                slot1 = 1 + (j / cw) * GRID_ + (c0 + j % cw);
            }
            const float4* q4  = (const float4*)(sQ + c * 64);
            const float4* kr0 = (const float4*)(sKV + slot0 * KSTR);
            const float4* kr1 = (const float4*)(sKV + slot1 * KSTR);
            float acc0 = 0.f, acc1 = 0.f;
#pragma unroll
            for (int i = 0; i < 16; i++) {
                const float4 qv = q4[i];
                const float4 k0 = kr0[i];
                const float4 k1 = kr1[i];
                acc0 += qv.x * k0.x + qv.y * k0.y + qv.z * k0.z + qv.w * k0.w;
                acc1 += qv.x * k1.x + qv.y * k1.y + qv.z * k1.z + qv.w * k1.w;
            }
            float s0 = (lane < cnt)      ? acc0 * 0.125f : -1e30f;
            float s1 = (lane + 32 < cnt) ? acc1 * 0.125f : -1e30f;

            float mx = fmaxf(s0, s1);
#pragma unroll
            for (int off = 16; off; off >>= 1)
                mx = fmaxf(mx, __shfl_xor_sync(0xffffffffu, mx, off));
            const float e0 = __expf(s0 - mx);
            const float e1 = __expf(s1 - mx);
            float sum = e0 + e1;
#pragma unroll
            for (int off = 16; off; off >>= 1)
                sum += __shfl_xor_sync(0xffffffffu, sum, off);
            const float inv = 1.0f / sum;

            pack[c * 64 + lane]      = make_float2(e0 * inv, __int_as_float(slot0));
            pack[c * 64 + lane + 32] = make_float2(e1 * inv, __int_as_float(slot1));
        }
        __syncthreads();

        // ---- phase 2: V band overwrites K ----
        for (int i = tid; i < nk * 16; i += 256) {
            const int slot = i >> 4;
            const int part = i & 15;
            const int gkey = (slot == 0) ? 0
                           : (1 + (r0 + (slot - 1) / GRID_) * GRID_ + (slot - 1) % GRID_);
            const float4 vv = *(const float4*)(g_QKV + krow0 + (size_t)gkey * (3 * C_) + voff + part * 4);
            *(float4*)(sKV + slot * KSTR + part * 4) = vv;
        }
        __syncthreads();

        for (int c = warp; c < GRID_; c += 8) {
            const int n = 1 + r * GRID_ + c;
            const size_t rowm = (size_t)b * N_ + n;
            const int c0 = (c - RAD_ < 0) ? 0 : c - RAD_;
            const int c1 = (c + RAD_ > GRID_ - 1) ? GRID_ - 1 : c + RAD_;
            const int cw = c1 - c0 + 1;
            const int cnt = 1 + span * cw;

            const float2* wp = pack + c * 64;
            float a0 = 0.f, a1 = 0.f;     // dims 2*lane, 2*lane+1
            for (int i = 0; i < cnt; i++) {
                const float2 ps = wp[i];
                const int slot = __float_as_int(ps.y);
                const float2 v = *(const float2*)(sKV + slot * KSTR + 2 * lane);
                a0 = fmaf(ps.x, v.x, a0);
                a1 = fmaf(ps.x, v.y, a1);
            }

            const size_t o = rowm * C_ + h * D_ + 2 * lane;
            const __half h0 = __float2half(a0);
            const __half h1 = __float2half(a1);
            __half2 hp; hp.x = h0; hp.y = h1;
            __half2 lp;
            lp.x = __float2half(a0 - __half2float(h0));
            lp.y = __float2half(a1 - __half2float(h1));
            *(__half2*)(g_Ohi + o) = hp;
            *(__half2*)(g_Olo + o) = lp;
        }
    } else {
        // ---------------- CLS CTA ----------------
        float* scores = sm;                 // [577] (+pad)
        float* partA  = sm + 640;           // [8][64]
        float* red    = sm + 640 + 8 * 64;  // [8]

        const int w2 = blk - NLOCALBLK;
        const int b  = w2 / H_;
        const int h  = w2 % H_;

        const size_t rowm = (size_t)b * N_;   // n = 0
        const float* qp = g_QKV + rowm * (3 * C_) + h * D_;
        const float q0 = qp[lane];
        const float q1 = qp[lane + 32];

        const size_t krow0 = (size_t)b * N_ * (3 * C_);
        const int koff = C_ + h * D_;
        const int voff = 2 * C_ + h * D_;

        for (int j = warp; j < N_; j += 8) {
            const float* kp = g_QKV + krow0 + (size_t)j * (3 * C_) + koff;
            float s = q0 * kp[lane] + q1 * kp[lane + 32];
#pragma unroll
            for (int off = 16; off; off >>= 1)
                s += __shfl_xor_sync(0xffffffffu, s, off);
            if (lane == 0) scores[j] = s * 0.125f;
        }
        __syncthreads();

        float mx = -1e30f;
        for (int i = tid; i < N_; i += 256) mx = fmaxf(mx, scores[i]);
#pragma unroll
        for (int off = 16; off; off >>= 1)
            mx = fmaxf(mx, __shfl_xor_sync(0xffffffffu, mx, off));
        if (lane == 0) red[warp] = mx;
        __syncthreads();
        mx = red[0];
#pragma unroll
        for (int w = 1; w < 8; w++) mx = fmaxf(mx, red[w]);
        __syncthreads();

        float lsum = 0.f;
        for (int i = tid; i < N_; i += 256) {
            float e = __expf(scores[i] - mx);
            scores[i] = e;
            lsum += e;
        }
#pragma unroll
        for (int off = 16; off; off >>= 1)
            lsum += __shfl_xor_sync(0xffffffffu, lsum, off);
        if (lane == 0) red[warp] = lsum;
        __syncthreads();
        float sum = 0.f;
#pragma unroll
        for (int w = 0; w < 8; w++) sum += red[w];
        const float inv = 1.0f / sum;

        float a0 = 0.f, a1 = 0.f;
        for (int j = warp; j < N_; j += 8) {
            const float p = scores[j];
            const float* vp = g_QKV + krow0 + (size_t)j * (3 * C_) + voff;
            a0 = fmaf(p, vp[lane],      a0);
            a1 = fmaf(p, vp[lane + 32], a1);
        }
        partA[warp * 64 + lane]      = a0;
        partA[warp * 64 + lane + 32] = a1;
        __syncthreads();

        if (warp == 0) {
            float t0 = 0.f, t1 = 0.f;
#pragma unroll
            for (int w = 0; w < 8; w++) {
                t0 += partA[w * 64 + lane];
                t1 += partA[w * 64 + lane + 32];
            }
            t0 *= inv; t1 *= inv;
            const size_t o = rowm * C_ + h * D_;
            const __half h0 = __float2half(t0);
            const __half h1 = __float2half(t1);
            g_Ohi[o + lane]      = h0;
            g_Olo[o + lane]      = __float2half(t0 - __half2float(h0));
            g_Ohi[o + lane + 32] = h1;
            g_Olo[o + lane + 32] = __float2half(t1 - __half2float(h1));
        }
    }
}

// ============================================================================
// launch
// ============================================================================
extern "C" void kernel_launch(void* const* d_in, const int* in_sizes, int n_in,
                              void* d_out, int out_size)
{
    const float* x     = (const float*)d_in[0];
    const float* Wqkv  = (const float*)d_in[1];
    const float* Wproj = (const float*)d_in[2];
    const float* bproj = (const float*)d_in[3];
    float* out = (float*)d_out;

    cudaFuncSetAttribute(hmma_gemm_kernel,
                         cudaFuncAttributeMaxDynamicSharedMemorySize, GEMM_SMEM);
    cudaFuncSetAttribute(attn_kernel,
                         cudaFuncAttributeMaxDynamicSharedMemorySize, ATT_SMEM);

    // 0) conversions
    __half *xhi, *xlo, *whi, *phi, *ohi, *olo;
    float* qkv;
    cudaGetSymbolAddress((void**)&xhi, g_xhi);
    cudaGetSymbolAddress((void**)&xlo, g_xlo);
    cudaGetSymbolAddress((void**)&whi, g_Whi);
    cudaGetSymbolAddress((void**)&phi, g_Phi);
    cudaGetSymbolAddress((void**)&ohi, g_Ohi);
    cudaGetSymbolAddress((void**)&olo, g_Olo);
    cudaGetSymbolAddress((void**)&qkv, g_QKV);

    {
        size_t total = (size_t)MPAD_ * K_;
        conv_x_kernel<<<(unsigned)((total + 255) / 256), 256>>>(x);
        conv_wT_kernel<<<dim3(3 * C_ / 32, K_ / 32), 256>>>(Wqkv, whi, 3 * C_);
        conv_wT_kernel<<<dim3(C_ / 32, K_ / 32), 256>>>(Wproj, phi, C_);
    }

    // 1) QKV GEMM: [M,768] @ [2304,768]^T -> g_QKV
    hmma_gemm_kernel<<<dim3(3 * C_ / 64, MT_), 256, GEMM_SMEM>>>(
        xhi, xlo, whi, nullptr, qkv, 3 * C_, M_);

    // 2) attention (local + CLS in one launch)
    attn_kernel<<<NLOCALBLK + B_ * H_, 256, ATT_SMEM>>>();

    // 3) proj GEMM: [M,768] @ [768,768]^T + bias -> out
    hmma_gemm_kernel<<<dim3(C_ / 64, MT_), 256, GEMM_SMEM>>>(
        ohi, olo, phi, bproj, out, C_, M_);
}

// round 11
// speedup vs baseline: 1.4766x; 1.0175x over previous
#include <cuda_runtime.h>
#include <cuda_fp16.h>
#include <cstdint>
#include <math.h>

// ---------------- problem constants ----------------
#define B_    32
#define N_    577
#define C_    768
#define H_    12
#define D_    64
#define GRID_ 24
#define RAD_  3
#define K_    768
#define M_    (B_*N_)      // 18464
#define MT_   145          // ceil(M/128)
#define MPAD_ (MT_*128)    // 18560

// ---------------- device-global scratch ----------------
__device__ __half  g_xhi[MPAD_*K_];
__device__ __half  g_xlo[MPAD_*K_];
__device__ __half  g_Whi[3*C_*K_];   // Wqkv^T  [2304,768] fp16
__device__ __half  g_Phi[C_*K_];     // Wproj^T [768,768]  fp16
__device__ __half  g_QKV[(size_t)M_*3*C_];      // [m, 2304] fp16 (85MB, L2-resident)
__device__ __half  g_Ohi[MPAD_*C_];
__device__ __half  g_Olo[MPAD_*C_];

// ---------------- PTX helpers ----------------
__device__ __forceinline__ uint32_t smem_u32(const void* p) {
    uint32_t a;
    asm("{ .reg .u64 t; cvta.to.shared.u64 t, %1; cvt.u32.u64 %0, t; }" : "=r"(a) : "l"(p));
    return a;
}
__device__ __forceinline__ void cp_async16(uint32_t dst, const void* src) {
    asm volatile("cp.async.cg.shared.global [%0], [%1], 16;" :: "r"(dst), "l"(src));
}
__device__ __forceinline__ void cp_commit() {
    asm volatile("cp.async.commit_group;");
}
template <int NN>
__device__ __forceinline__ void cp_wait() {
    asm volatile("cp.async.wait_group %0;" :: "n"(NN));
}
__device__ __forceinline__ void ldmatrix_x4(uint32_t& r0, uint32_t& r1,
                                            uint32_t& r2, uint32_t& r3, uint32_t addr) {
    asm volatile("ldmatrix.sync.aligned.m8n8.x4.shared.b16 {%0,%1,%2,%3}, [%4];"
                 : "=r"(r0), "=r"(r1), "=r"(r2), "=r"(r3) : "r"(addr));
}
__device__ __forceinline__ void mma_fp16(float* c, const uint32_t* a,
                                         uint32_t b0, uint32_t b1) {
    asm volatile(
        "mma.sync.aligned.m16n8k16.row.col.f32.f16.f16.f32 "
        "{%0,%1,%2,%3}, {%4,%5,%6,%7}, {%8,%9}, {%0,%1,%2,%3};"
        : "+f"(c[0]), "+f"(c[1]), "+f"(c[2]), "+f"(c[3])
        : "r"(a[0]), "r"(a[1]), "r"(a[2]), "r"(a[3]), "r"(b0), "r"(b1));
}

// ============================================================================
// conversion kernels
// ============================================================================
__global__ void conv_x_kernel(const float* __restrict__ x) {
    size_t idx = (size_t)blockIdx.x * 256 + threadIdx.x;
    if (idx >= (size_t)MPAD_ * K_) return;
    size_t m = idx / K_;
    if (m < M_) {
        float a = x[idx];
        __half hi = __float2half(a);
        __half lo = __float2half(a - __half2float(hi));
        g_xhi[idx] = hi;
        g_xlo[idx] = lo;
    } else {
        g_xhi[idx] = __float2half(0.f);
        g_xlo[idx] = __float2half(0.f);
        g_Ohi[idx] = __float2half(0.f);   // same index space [MPAD*768]
        g_Olo[idx] = __float2half(0.f);
    }
}

// transpose-convert: W [K_, Ncols] fp32 -> T [Ncols, K_] fp16 (hi only)
__global__ void conv_wT_kernel(const float* __restrict__ W,
                               __half* __restrict__ Thi, int Ncols) {
    __shared__ float t[32][33];
    const int kc = blockIdx.y * 32;
    const int nc = blockIdx.x * 32;
    const int tx = threadIdx.x & 31;
    const int ty = threadIdx.x >> 5;
    for (int i = ty; i < 32; i += 8)
        t[i][tx] = W[(size_t)(kc + i) * Ncols + nc + tx];
    __syncthreads();
    for (int i = ty; i < 32; i += 8) {
        size_t o = (size_t)(nc + i) * K_ + kc + tx;
        Thi[o] = __float2half(t[tx][i]);
    }
}

// ============================================================================
// fp16 2-term HMMA GEMM: C = (Ahi+Alo) @ Bhi^T (+bias)
// 128x64x64 tiles, 2-stage cp.async, 2 CTAs/SM
// HALF_OUT=1: write __half (no bias);  HALF_OUT=0: write float + bias
// ============================================================================
#define NCHUNK   (K_/64)          // 12
#define A_B      (128*128)
#define B_B      (64*128)
#define STAGE_B  (2*A_B + B_B)    // 40KB
#define GEMM_SMEM (2*STAGE_B)     // 80KB

template <int HALF_OUT>
__global__ __launch_bounds__(256, 2)
void hmma_gemm_kernel(const __half* __restrict__ Ahi,
                      const __half* __restrict__ Alo,
                      const __half* __restrict__ Bh,
                      const float* __restrict__ bias,
                      void* __restrict__ CoutV,
                      int Ncols, int Mrows)
{
    extern __shared__ unsigned char smem[];
    const uint32_t s_base = smem_u32(smem);

    const int tid   = threadIdx.x;
    const int wid   = tid >> 5;
    const int lane  = tid & 31;
    const int m0    = blockIdx.y * 128;
    const int n0    = blockIdx.x * 64;
    const int wm    = (wid >> 1) * 32;
    const int wn    = (wid & 1) * 32;

    const int lr = tid >> 3;
    const int lc = tid & 7;
    auto load_stage = [&](int st, int kc) {
        const uint32_t sb = s_base + st * STAGE_B;
        const int k0 = kc * 64 + lc * 8;
#pragma unroll
        for (int i = 0; i < 4; i++) {
            const int row = lr + i * 32;
            const uint32_t so = row * 128 + ((lc ^ (row & 7)) << 4);
            const size_t ga = (size_t)(m0 + row) * K_ + k0;
            cp_async16(sb + so,        Ahi + ga);
            cp_async16(sb + A_B + so,  Alo + ga);
        }
#pragma unroll
        for (int i = 0; i < 2; i++) {
            const int row = lr + i * 32;
            const uint32_t so = row * 128 + ((lc ^ (row & 7)) << 4);
            const size_t gb = (size_t)(n0 + row) * K_ + k0;
            cp_async16(sb + 2*A_B + so, Bh + gb);
        }
    };

    float acc[2][4][4];
#pragma unroll
    for (int i = 0; i < 2; i++)
#pragma unroll
        for (int j = 0; j < 4; j++)
#pragma unroll
            for (int v = 0; v < 4; v++) acc[i][j][v] = 0.f;

    load_stage(0, 0); cp_commit();

    const int a_row = (lane & 15);
    const int a_chi = (lane >> 4);
    const int b_row = (lane & 7) + ((lane >> 4) << 3);
    const int b_chi = (lane >> 3) & 1;

    for (int kc = 0; kc < NCHUNK; kc++) {
        if (kc + 1 < NCHUNK) {
            load_stage((kc + 1) & 1, kc + 1);
            cp_commit();
            cp_wait<1>();
        } else {
            cp_wait<0>();
        }
        __syncthreads();

        const uint32_t sb   = s_base + (kc & 1) * STAGE_B;
        const uint32_t sAhi = sb;
        const uint32_t sAlo = sb + A_B;
        const uint32_t sBh  = sb + 2*A_B;

#pragma unroll
        for (int s = 0; s < 4; s++) {
            uint32_t fah[2][4], fal[2][4];
#pragma unroll
            for (int mi = 0; mi < 2; mi++) {
                const int row = wm + mi * 16 + a_row;
                const int ch  = (2 * s + a_chi) ^ (row & 7);
                const uint32_t off = row * 128 + (ch << 4);
                ldmatrix_x4(fah[mi][0], fah[mi][1], fah[mi][2], fah[mi][3], sAhi + off);
                ldmatrix_x4(fal[mi][0], fal[mi][1], fal[mi][2], fal[mi][3], sAlo + off);
            }
            uint32_t fbh[2][4];
#pragma unroll
            for (int ng = 0; ng < 2; ng++) {
                const int row = wn + ng * 16 + b_row;
                const int ch  = (2 * s + b_chi) ^ (row & 7);
                const uint32_t off = row * 128 + (ch << 4);
                ldmatrix_x4(fbh[ng][0], fbh[ng][1], fbh[ng][2], fbh[ng][3], sBh + off);
            }
#pragma unroll
            for (int mi = 0; mi < 2; mi++) {
#pragma unroll
                for (int ng = 0; ng < 2; ng++) {
#pragma unroll
                    for (int hh = 0; hh < 2; hh++) {
                        float* c = acc[mi][ng * 2 + hh];
                        const uint32_t b0 = fbh[ng][hh * 2], b1 = fbh[ng][hh * 2 + 1];
                        mma_fp16(c, fah[mi], b0, b1);
                        mma_fp16(c, fal[mi], b0, b1);
                    }
                }
            }
        }
        __syncthreads();
    }

#pragma unroll
    for (int ni = 0; ni < 4; ni++) {
        const int col = n0 + wn + ni * 8 + (lane & 3) * 2;
        if (HALF_OUT) {
            __half* Cout = (__half*)CoutV;
#pragma unroll
            for (int mi = 0; mi < 2; mi++) {
                const int r0 = m0 + wm + mi * 16 + (lane >> 2);
                if (r0 < Mrows) {
                    __half2 v; v.x = __float2half(acc[mi][ni][0]); v.y = __float2half(acc[mi][ni][1]);
                    *(__half2*)(Cout + (size_t)r0 * Ncols + col) = v;
                }
                const int r1 = r0 + 8;
                if (r1 < Mrows) {
                    __half2 v; v.x = __float2half(acc[mi][ni][2]); v.y = __float2half(acc[mi][ni][3]);
                    *(__half2*)(Cout + (size_t)r1 * Ncols + col) = v;
                }
            }
        } else {
            float* Cout = (float*)CoutV;
            const float bx = bias ? bias[col]     : 0.f;
            const float by = bias ? bias[col + 1] : 0.f;
#pragma unroll
            for (int mi = 0; mi < 2; mi++) {
                const int r0 = m0 + wm + mi * 16 + (lane >> 2);
                if (r0 < Mrows) {
                    float2 v = make_float2(acc[mi][ni][0] + bx, acc[mi][ni][1] + by);
                    *(float2*)(Cout + (size_t)r0 * Ncols + col) = v;
                }
                const int r1 = r0 + 8;
                if (r1 < Mrows) {
                    float2 v = make_float2(acc[mi][ni][2] + bx, acc[mi][ni][3] + by);
                    *(float2*)(Cout + (size_t)r1 * Ncols + col) = v;
                }
            }
        }
    }
}

// ============================================================================
// merged attention kernel (R7/R10 structure; g_QKV now fp16, smem fp32)
//   blk <  B*H*GRID  : local-row CTA (two-pass K/V smem reuse, 8 warps x 3 q)
//   blk >= B*H*GRID  : CLS CTA for (b,h)
// ============================================================================
#define MAXNK     169
#define KSTR      68
#define NLOCALBLK (B_*H_*GRID_)      // 9216
#define SQ_F      (24*64)
#define SKV_F     (MAXNK*KSTR)
#define ATT_SMEM  ((SQ_F + SKV_F + 24*64*2) * 4)   // ~64KB

// load 8 halves from global, convert, store 8 floats to smem
__device__ __forceinline__ void h8_to_smem(float* dst, const __half* src) {
    const uint4 raw = *(const uint4*)src;
    const __half2* h2 = (const __half2*)&raw;
    const float2 f0 = __half22float2(h2[0]);
    const float2 f1 = __half22float2(h2[1]);
    const float2 f2 = __half22float2(h2[2]);
    const float2 f3 = __half22float2(h2[3]);
    *(float4*)dst       = make_float4(f0.x, f0.y, f1.x, f1.y);
    *(float4*)(dst + 4) = make_float4(f2.x, f2.y, f3.x, f3.y);
}

__global__ __launch_bounds__(256, 3)
void attn_kernel()
{
    extern __shared__ float sm[];

    const int tid  = threadIdx.x;
    const int lane = tid & 31;
    const int warp = tid >> 5;
    const int blk  = blockIdx.x;

    if (blk < NLOCALBLK) {
        float*  sQ   = sm;                           // [24][64]
        float*  sKV  = sm + SQ_F;                    // [169][68]
        float2* pack = (float2*)(sm + SQ_F + SKV_F); // [24][64] (prob, slot)

        const int r = blk % GRID_;
        const int h = (blk / GRID_) % H_;
        const int b = blk / (GRID_ * H_);

        const int r0   = (r - RAD_ < 0) ? 0 : r - RAD_;
        const int r1   = (r + RAD_ > GRID_ - 1) ? GRID_ - 1 : r + RAD_;
        const int span = r1 - r0 + 1;
        const int nk   = span * GRID_ + 1;

        const size_t krow0 = (size_t)b * N_ * (3 * C_);
        const int koff = C_ + h * D_;
        const int voff = 2 * C_ + h * D_;
        const size_t qbase = ((size_t)b * N_ + 1 + r * GRID_) * (3 * C_) + h * D_;

        // ---- phase 0: queries (fp16 -> fp32 smem) ----
        for (int i = tid; i < 24 * 8; i += 256) {
            const int c    = i >> 3;
            const int part = i & 7;
            h8_to_smem(sQ + c * 64 + part * 8,
                       g_QKV + qbase + (size_t)c * (3 * C_) + part * 8);
        }
        // ---- phase 1: K band ----
        for (int i = tid; i < nk * 8; i += 256) {
            const int slot = i >> 3;
            const int part = i & 7;
            const int gkey = (slot == 0) ? 0
                           : (1 + (r0 + (slot - 1) / GRID_) * GRID_ + (slot - 1) % GRID_);
            h8_to_smem(sKV + slot * KSTR + part * 8,
                       g_QKV + krow0 + (size_t)gkey * (3 * C_) + koff + part * 8);
        }
        __syncthreads();

        for (int c = warp; c < GRID_; c += 8) {
            const int c0 = (c - RAD_ < 0) ? 0 : c - RAD_;
            const int c1 = (c + RAD_ > GRID_ - 1) ? GRID_ - 1 : c + RAD_;
            const int cw = c1 - c0 + 1;
            const int cnt = 1 + span * cw;

            int slot0 = 0, slot1 = 0;
            if (lane > 0 && lane < cnt) {
                const int j = lane - 1;
                slot0 = 1 + (j / cw) * GRID_ + (c0 + j % cw);
            }
            if (lane + 32 < cnt) {
                const int j = lane + 31;
                slot1 = 1 + (j / cw) * GRID_ + (c0 + j % cw);
            }
            const float4* q4  = (const float4*)(sQ + c * 64);
            const float4* kr0 = (const float4*)(sKV + slot0 * KSTR);
            const float4* kr1 = (const float4*)(sKV + slot1 * KSTR);
            float acc0 = 0.f, acc1 = 0.f;
#pragma unroll
            for (int i = 0; i < 16; i++) {
                const float4 qv = q4[i];
                const float4 k0 = kr0[i];
                const float4 k1 = kr1[i];
                acc0 += qv.x * k0.x + qv.y * k0.y + qv.z * k0.z + qv.w * k0.w;
                acc1 += qv.x * k1.x + qv.y * k1.y + qv.z * k1.z + qv.w * k1.w;
            }
            float s0 = (lane < cnt)      ? acc0 * 0.125f : -1e30f;
            float s1 = (lane + 32 < cnt) ? acc1 * 0.125f : -1e30f;

            float mx = fmaxf(s0, s1);
#pragma unroll
            for (int off = 16; off; off >>= 1)
                mx = fmaxf(mx, __shfl_xor_sync(0xffffffffu, mx, off));
            const float e0 = __expf(s0 - mx);
            const float e1 = __expf(s1 - mx);
            float sum = e0 + e1;
#pragma unroll
            for (int off = 16; off; off >>= 1)
                sum += __shfl_xor_sync(0xffffffffu, sum, off);
            const float inv = 1.0f / sum;

            pack[c * 64 + lane]      = make_float2(e0 * inv, __int_as_float(slot0));
            pack[c * 64 + lane + 32] = make_float2(e1 * inv, __int_as_float(slot1));
        }
        __syncthreads();

        // ---- phase 2: V band overwrites K ----
        for (int i = tid; i < nk * 8; i += 256) {
            const int slot = i >> 3;
            const int part = i & 7;
            const int gkey = (slot == 0) ? 0
                           : (1 + (r0 + (slot - 1) / GRID_) * GRID_ + (slot - 1) % GRID_);
            h8_to_smem(sKV + slot * KSTR + part * 8,
                       g_QKV + krow0 + (size_t)gkey * (3 * C_) + voff + part * 8);
        }
        __syncthreads();

        for (int c = warp; c < GRID_; c += 8) {
            const int n = 1 + r * GRID_ + c;
            const size_t rowm = (size_t)b * N_ + n;
            const int c0 = (c - RAD_ < 0) ? 0 : c - RAD_;
            const int c1 = (c + RAD_ > GRID_ - 1) ? GRID_ - 1 : c + RAD_;
            const int cw = c1 - c0 + 1;
            const int cnt = 1 + span * cw;

            const float2* wp = pack + c * 64;
            float a0 = 0.f, a1 = 0.f;     // dims 2*lane, 2*lane+1
            for (int i = 0; i < cnt; i++) {
                const float2 ps = wp[i];
                const int slot = __float_as_int(ps.y);
                const float2 v = *(const float2*)(sKV + slot * KSTR + 2 * lane);
                a0 = fmaf(ps.x, v.x, a0);
                a1 = fmaf(ps.x, v.y, a1);
            }

            const size_t o = rowm * C_ + h * D_ + 2 * lane;
            const __half h0 = __float2half(a0);
            const __half h1 = __float2half(a1);
            __half2 hp; hp.x = h0; hp.y = h1;
            __half2 lp;
            lp.x = __float2half(a0 - __half2float(h0));
            lp.y = __float2half(a1 - __half2float(h1));
            *(__half2*)(g_Ohi + o) = hp;
            *(__half2*)(g_Olo + o) = lp;
        }
    } else {
        // ---------------- CLS CTA ----------------
        float* scores = sm;                 // [577] (+pad)
        float* partA  = sm + 640;           // [8][64]
        float* red    = sm + 640 + 8 * 64;  // [8]

        const int w2 = blk - NLOCALBLK;
        const int b  = w2 / H_;
        const int h  = w2 % H_;

        const size_t rowm = (size_t)b * N_;   // n = 0
        const __half* qp = g_QKV + rowm * (3 * C_) + h * D_;
        const float q0 = __half2float(qp[lane]);
        const float q1 = __half2float(qp[lane + 32]);

        const size_t krow0 = (size_t)b * N_ * (3 * C_);
        const int koff = C_ + h * D_;
        const int voff = 2 * C_ + h * D_;

        for (int j = warp; j < N_; j += 8) {
            const __half* kp = g_QKV + krow0 + (size_t)j * (3 * C_) + koff;
            float s = q0 * __half2float(kp[lane]) + q1 * __half2float(kp[lane + 32]);
#pragma unroll
            for (int off = 16; off; off >>= 1)
                s += __shfl_xor_sync(0xffffffffu, s, off);
            if (lane == 0) scores[j] = s * 0.125f;
        }
        __syncthreads();

        float mx = -1e30f;
        for (int i = tid; i < N_; i += 256) mx = fmaxf(mx, scores[i]);
#pragma unroll
        for (int off = 16; off; off >>= 1)
            mx = fmaxf(mx, __shfl_xor_sync(0xffffffffu, mx, off));
        if (lane == 0) red[warp] = mx;
        __syncthreads();
        mx = red[0];
#pragma unroll
        for (int w = 1; w < 8; w++) mx = fmaxf(mx, red[w]);
        __syncthreads();

        float lsum = 0.f;
        for (int i = tid; i < N_; i += 256) {
            float e = __expf(scores[i] - mx);
            scores[i] = e;
            lsum += e;
        }
#pragma unroll
        for (int off = 16; off; off >>= 1)
            lsum += __shfl_xor_sync(0xffffffffu, lsum, off);
        if (lane == 0) red[warp] = lsum;
        __syncthreads();
        float sum = 0.f;
#pragma unroll
        for (int w = 0; w < 8; w++) sum += red[w];
        const float inv = 1.0f / sum;

        float a0 = 0.f, a1 = 0.f;
        for (int j = warp; j < N_; j += 8) {
            const float p = scores[j];
            const __half* vp = g_QKV + krow0 + (size_t)j * (3 * C_) + voff;
            a0 = fmaf(p, __half2float(vp[lane]),      a0);
            a1 = fmaf(p, __half2float(vp[lane + 32]), a1);
        }
        partA[warp * 64 + lane]      = a0;
        partA[warp * 64 + lane + 32] = a1;
        __syncthreads();

        if (warp == 0) {
            float t0 = 0.f, t1 = 0.f;
#pragma unroll
            for (int w = 0; w < 8; w++) {
                t0 += partA[w * 64 + lane];
                t1 += partA[w * 64 + lane + 32];
            }
            t0 *= inv; t1 *= inv;
            const size_t o = rowm * C_ + h * D_;
            const __half h0 = __float2half(t0);
            const __half h1 = __float2half(t1);
            g_Ohi[o + lane]      = h0;
            g_Olo[o + lane]      = __float2half(t0 - __half2float(h0));
            g_Ohi[o + lane + 32] = h1;
            g_Olo[o + lane + 32] = __float2half(t1 - __half2float(h1));
        }
    }
}

// ============================================================================
// launch
// ============================================================================
extern "C" void kernel_launch(void* const* d_in, const int* in_sizes, int n_in,
                              void* d_out, int out_size)
{
    const float* x     = (const float*)d_in[0];
    const float* Wqkv  = (const float*)d_in[1];
    const float* Wproj = (const float*)d_in[2];
    const float* bproj = (const float*)d_in[3];
    float* out = (float*)d_out;

    cudaFuncSetAttribute(hmma_gemm_kernel<0>,
                         cudaFuncAttributeMaxDynamicSharedMemorySize, GEMM_SMEM);
    cudaFuncSetAttribute(hmma_gemm_kernel<1>,
                         cudaFuncAttributeMaxDynamicSharedMemorySize, GEMM_SMEM);
    cudaFuncSetAttribute(attn_kernel,
                         cudaFuncAttributeMaxDynamicSharedMemorySize, ATT_SMEM);

    __half *xhi, *xlo, *whi, *phi, *ohi, *olo, *qkv;
    cudaGetSymbolAddress((void**)&xhi, g_xhi);
    cudaGetSymbolAddress((void**)&xlo, g_xlo);
    cudaGetSymbolAddress((void**)&whi, g_Whi);
    cudaGetSymbolAddress((void**)&phi, g_Phi);
    cudaGetSymbolAddress((void**)&ohi, g_Ohi);
    cudaGetSymbolAddress((void**)&olo, g_Olo);
    cudaGetSymbolAddress((void**)&qkv, g_QKV);

    // 0) conversions
    {
        size_t total = (size_t)MPAD_ * K_;
        conv_x_kernel<<<(unsigned)((total + 255) / 256), 256>>>(x);
        conv_wT_kernel<<<dim3(3 * C_ / 32, K_ / 32), 256>>>(Wqkv, whi, 3 * C_);
        conv_wT_kernel<<<dim3(C_ / 32, K_ / 32), 256>>>(Wproj, phi, C_);
    }

    // 1) QKV GEMM: [M,768] @ [2304,768]^T -> g_QKV (fp16)
    hmma_gemm_kernel<1><<<dim3(3 * C_ / 64, MT_), 256, GEMM_SMEM>>>(
        xhi, xlo, whi, nullptr, qkv, 3 * C_, M_);

    // 2) attention (local + CLS in one launch)
    attn_kernel<<<NLOCALBLK + B_ * H_, 256, ATT_SMEM>>>();

    // 3) proj GEMM: [M,768] @ [768,768]^T + bias -> out (fp32)
    hmma_gemm_kernel<0><<<dim3(C_ / 64, MT_), 256, GEMM_SMEM>>>(
        ohi, olo, phi, bproj, out, C_, M_);
}

// round 12
// speedup vs baseline: 1.7649x; 1.1953x over previous
#include <cuda_runtime.h>
#include <cuda_fp16.h>
#include <cstdint>
#include <math.h>

// ---------------- problem constants ----------------
#define B_    32
#define N_    577
#define C_    768
#define H_    12
#define D_    64
#define GRID_ 24
#define RAD_  3
#define K_    768
#define M_    (B_*N_)      // 18464
#define MT_   145          // ceil(M/128)
#define MPAD_ (MT_*128)    // 18560

// ---------------- device-global scratch ----------------
__device__ __half  g_xhi[MPAD_*K_];
__device__ __half  g_xlo[MPAD_*K_];
__device__ __half  g_Whi[3*C_*K_];   // Wqkv^T  [2304,768] fp16
__device__ __half  g_Phi[C_*K_];     // Wproj^T [768,768]  fp16
__device__ __half  g_QKV[(size_t)M_*3*C_];      // [m, 2304] fp16
__device__ __half  g_Ohi[MPAD_*C_];
__device__ __half  g_Olo[MPAD_*C_];

// ---------------- PTX helpers ----------------
__device__ __forceinline__ uint32_t smem_u32(const void* p) {
    uint32_t a;
    asm("{ .reg .u64 t; cvta.to.shared.u64 t, %1; cvt.u32.u64 %0, t; }" : "=r"(a) : "l"(p));
    return a;
}
__device__ __forceinline__ void cp_async16(uint32_t dst, const void* src) {
    asm volatile("cp.async.cg.shared.global [%0], [%1], 16;" :: "r"(dst), "l"(src));
}
__device__ __forceinline__ void cp_commit() {
    asm volatile("cp.async.commit_group;");
}
template <int NN>
__device__ __forceinline__ void cp_wait() {
    asm volatile("cp.async.wait_group %0;" :: "n"(NN));
}
__device__ __forceinline__ void ldmatrix_x4(uint32_t& r0, uint32_t& r1,
                                            uint32_t& r2, uint32_t& r3, uint32_t addr) {
    asm volatile("ldmatrix.sync.aligned.m8n8.x4.shared.b16 {%0,%1,%2,%3}, [%4];"
                 : "=r"(r0), "=r"(r1), "=r"(r2), "=r"(r3) : "r"(addr));
}
__device__ __forceinline__ void mma_fp16(float* c, const uint32_t* a,
                                         uint32_t b0, uint32_t b1) {
    asm volatile(
        "mma.sync.aligned.m16n8k16.row.col.f32.f16.f16.f32 "
        "{%0,%1,%2,%3}, {%4,%5,%6,%7}, {%8,%9}, {%0,%1,%2,%3};"
        : "+f"(c[0]), "+f"(c[1]), "+f"(c[2]), "+f"(c[3])
        : "r"(a[0]), "r"(a[1]), "r"(a[2]), "r"(a[3]), "r"(b0), "r"(b1));
}

// ============================================================================
// conversion kernels
// ============================================================================
__global__ void conv_x_kernel(const float* __restrict__ x) {
    size_t idx = (size_t)blockIdx.x * 256 + threadIdx.x;
    if (idx >= (size_t)MPAD_ * K_) return;
    size_t m = idx / K_;
    if (m < M_) {
        float a = x[idx];
        __half hi = __float2half(a);
        __half lo = __float2half(a - __half2float(hi));
        g_xhi[idx] = hi;
        g_xlo[idx] = lo;
    } else {
        g_xhi[idx] = __float2half(0.f);
        g_xlo[idx] = __float2half(0.f);
        g_Ohi[idx] = __float2half(0.f);
        g_Olo[idx] = __float2half(0.f);
    }
}

__global__ void conv_wT_kernel(const float* __restrict__ W,
                               __half* __restrict__ Thi, int Ncols) {
    __shared__ float t[32][33];
    const int kc = blockIdx.y * 32;
    const int nc = blockIdx.x * 32;
    const int tx = threadIdx.x & 31;
    const int ty = threadIdx.x >> 5;
    for (int i = ty; i < 32; i += 8)
        t[i][tx] = W[(size_t)(kc + i) * Ncols + nc + tx];
    __syncthreads();
    for (int i = ty; i < 32; i += 8) {
        size_t o = (size_t)(nc + i) * K_ + kc + tx;
        Thi[o] = __float2half(t[tx][i]);
    }
}

// ============================================================================
// fp16 2-term HMMA GEMM: C = (Ahi+Alo) @ Bhi^T (+bias)  (unchanged from R11)
// ============================================================================
#define NCHUNK   (K_/64)
#define A_B      (128*128)
#define B_B      (64*128)
#define STAGE_B  (2*A_B + B_B)
#define GEMM_SMEM (2*STAGE_B)

template <int HALF_OUT>
__global__ __launch_bounds__(256, 2)
void hmma_gemm_kernel(const __half* __restrict__ Ahi,
                      const __half* __restrict__ Alo,
                      const __half* __restrict__ Bh,
                      const float* __restrict__ bias,
                      void* __restrict__ CoutV,
                      int Ncols, int Mrows)
{
    extern __shared__ unsigned char smem[];
    const uint32_t s_base = smem_u32(smem);

    const int tid   = threadIdx.x;
    const int wid   = tid >> 5;
    const int lane  = tid & 31;
    const int m0    = blockIdx.y * 128;
    const int n0    = blockIdx.x * 64;
    const int wm    = (wid >> 1) * 32;
    const int wn    = (wid & 1) * 32;

    const int lr = tid >> 3;
    const int lc = tid & 7;
    auto load_stage = [&](int st, int kc) {
        const uint32_t sb = s_base + st * STAGE_B;
        const int k0 = kc * 64 + lc * 8;
#pragma unroll
        for (int i = 0; i < 4; i++) {
            const int row = lr + i * 32;
            const uint32_t so = row * 128 + ((lc ^ (row & 7)) << 4);
            const size_t ga = (size_t)(m0 + row) * K_ + k0;
            cp_async16(sb + so,        Ahi + ga);
            cp_async16(sb + A_B + so,  Alo + ga);
        }
#pragma unroll
        for (int i = 0; i < 2; i++) {
            const int row = lr + i * 32;
            const uint32_t so = row * 128 + ((lc ^ (row & 7)) << 4);
            const size_t gb = (size_t)(n0 + row) * K_ + k0;
            cp_async16(sb + 2*A_B + so, Bh + gb);
        }
    };

    float acc[2][4][4];
#pragma unroll
    for (int i = 0; i < 2; i++)
#pragma unroll
        for (int j = 0; j < 4; j++)
#pragma unroll
            for (int v = 0; v < 4; v++) acc[i][j][v] = 0.f;

    load_stage(0, 0); cp_commit();

    const int a_row = (lane & 15);
    const int a_chi = (lane >> 4);
    const int b_row = (lane & 7) + ((lane >> 4) << 3);
    const int b_chi = (lane >> 3) & 1;

    for (int kc = 0; kc < NCHUNK; kc++) {
        if (kc + 1 < NCHUNK) {
            load_stage((kc + 1) & 1, kc + 1);
            cp_commit();
            cp_wait<1>();
        } else {
            cp_wait<0>();
        }
        __syncthreads();

        const uint32_t sb   = s_base + (kc & 1) * STAGE_B;
        const uint32_t sAhi = sb;
        const uint32_t sAlo = sb + A_B;
        const uint32_t sBh  = sb + 2*A_B;

#pragma unroll
        for (int s = 0; s < 4; s++) {
            uint32_t fah[2][4], fal[2][4];
#pragma unroll
            for (int mi = 0; mi < 2; mi++) {
                const int row = wm + mi * 16 + a_row;
                const int ch  = (2 * s + a_chi) ^ (row & 7);
                const uint32_t off = row * 128 + (ch << 4);
                ldmatrix_x4(fah[mi][0], fah[mi][1], fah[mi][2], fah[mi][3], sAhi + off);
                ldmatrix_x4(fal[mi][0], fal[mi][1], fal[mi][2], fal[mi][3], sAlo + off);
            }
            uint32_t fbh[2][4];
#pragma unroll
            for (int ng = 0; ng < 2; ng++) {
                const int row = wn + ng * 16 + b_row;
                const int ch  = (2 * s + b_chi) ^ (row & 7);
                const uint32_t off = row * 128 + (ch << 4);
                ldmatrix_x4(fbh[ng][0], fbh[ng][1], fbh[ng][2], fbh[ng][3], sBh + off);
            }
#pragma unroll
            for (int mi = 0; mi < 2; mi++) {
#pragma unroll
                for (int ng = 0; ng < 2; ng++) {
#pragma unroll
                    for (int hh = 0; hh < 2; hh++) {
                        float* c = acc[mi][ng * 2 + hh];
                        const uint32_t b0 = fbh[ng][hh * 2], b1 = fbh[ng][hh * 2 + 1];
                        mma_fp16(c, fah[mi], b0, b1);
                        mma_fp16(c, fal[mi], b0, b1);
                    }
                }
            }
        }
        __syncthreads();
    }

#pragma unroll
    for (int ni = 0; ni < 4; ni++) {
        const int col = n0 + wn + ni * 8 + (lane & 3) * 2;
        if (HALF_OUT) {
            __half* Cout = (__half*)CoutV;
#pragma unroll
            for (int mi = 0; mi < 2; mi++) {
                const int r0 = m0 + wm + mi * 16 + (lane >> 2);
                if (r0 < Mrows) {
                    __half2 v; v.x = __float2half(acc[mi][ni][0]); v.y = __float2half(acc[mi][ni][1]);
                    *(__half2*)(Cout + (size_t)r0 * Ncols + col) = v;
                }
                const int r1 = r0 + 8;
                if (r1 < Mrows) {
                    __half2 v; v.x = __float2half(acc[mi][ni][2]); v.y = __float2half(acc[mi][ni][3]);
                    *(__half2*)(Cout + (size_t)r1 * Ncols + col) = v;
                }
            }
        } else {
            float* Cout = (float*)CoutV;
            const float bx = bias ? bias[col]     : 0.f;
            const float by = bias ? bias[col + 1] : 0.f;
#pragma unroll
            for (int mi = 0; mi < 2; mi++) {
                const int r0 = m0 + wm + mi * 16 + (lane >> 2);
                if (r0 < Mrows) {
                    float2 v = make_float2(acc[mi][ni][0] + bx, acc[mi][ni][1] + by);
                    *(float2*)(Cout + (size_t)r0 * Ncols + col) = v;
                }
                const int r1 = r0 + 8;
                if (r1 < Mrows) {
                    float2 v = make_float2(acc[mi][ni][2] + bx, acc[mi][ni][3] + by);
                    *(float2*)(Cout + (size_t)r1 * Ncols + col) = v;
                }
            }
        }
    }
}

// ============================================================================
// merged attention kernel — single-pass cp.async fill, fp16 smem K+V
//   blk <  B*H*GRID  : local-row CTA
//   blk >= B*H*GRID  : CLS CTA for (b,h)
// smem: sQ half[24*64] | sK half[169*72] | sV half[169*72] | pack float2[24*64]
// ============================================================================
#define MAXNK     169
#define KSTRH     72                 // halves per K/V row (144B)
#define NLOCALBLK (B_*H_*GRID_)      // 9216
#define SQ_H      (24*64)            // 1536 halves (3072B)
#define SKV_H     (MAXNK*KSTRH)      // 12168 halves (24336B)
#define ATT_SMEM  (SQ_H*2 + 2*SKV_H*2 + 24*64*8)   // 3072+48672+12288 = 64032B

__global__ __launch_bounds__(256, 3)
void attn_kernel()
{
    extern __shared__ unsigned char smraw[];

    const int tid  = threadIdx.x;
    const int lane = tid & 31;
    const int warp = tid >> 5;
    const int blk  = blockIdx.x;

    if (blk < NLOCALBLK) {
        __half* sQ  = (__half*)smraw;                       // [24][64]
        __half* sK  = sQ + SQ_H;                            // [169][72]
        __half* sV  = sK + SKV_H;                           // [169][72]
        float2* pack = (float2*)(smraw + SQ_H*2 + 2*SKV_H*2); // [24][64]
        const uint32_t aQ = smem_u32(sQ);
        const uint32_t aK = smem_u32(sK);
        const uint32_t aV = smem_u32(sV);

        const int r = blk % GRID_;
        const int h = (blk / GRID_) % H_;
        const int b = blk / (GRID_ * H_);

        const int r0   = (r - RAD_ < 0) ? 0 : r - RAD_;
        const int r1   = (r + RAD_ > GRID_ - 1) ? GRID_ - 1 : r + RAD_;
        const int span = r1 - r0 + 1;
        const int nk   = span * GRID_ + 1;

        const size_t krow0 = (size_t)b * N_ * (3 * C_);
        const int koff = C_ + h * D_;
        const int voff = 2 * C_ + h * D_;
        const size_t qbase = ((size_t)b * N_ + 1 + r * GRID_) * (3 * C_) + h * D_;

        // ---- single async fill: queries + K band + V band ----
        for (int i = tid; i < 24 * 8; i += 256) {
            const int c    = i >> 3;
            const int part = i & 7;
            cp_async16(aQ + (uint32_t)(c * 64 + part * 8) * 2,
                       g_QKV + qbase + (size_t)c * (3 * C_) + part * 8);
        }
        for (int i = tid; i < nk * 8; i += 256) {
            const int slot = i >> 3;
            const int part = i & 7;
            const int gkey = (slot == 0) ? 0
                           : (1 + (r0 + (slot - 1) / GRID_) * GRID_ + (slot - 1) % GRID_);
            const __half* gp = g_QKV + krow0 + (size_t)gkey * (3 * C_);
            const uint32_t so = (uint32_t)(slot * KSTRH + part * 8) * 2;
            cp_async16(aK + so, gp + koff + part * 8);
            cp_async16(aV + so, gp + voff + part * 8);
        }
        cp_commit();
        cp_wait<0>();
        __syncthreads();

        // ---- QK + softmax ----
        for (int c = warp; c < GRID_; c += 8) {
            const int c0 = (c - RAD_ < 0) ? 0 : c - RAD_;
            const int c1 = (c + RAD_ > GRID_ - 1) ? GRID_ - 1 : c + RAD_;
            const int cw = c1 - c0 + 1;
            const int cnt = 1 + span * cw;

            int slot0 = 0, slot1 = 0;
            if (lane > 0 && lane < cnt) {
                const int j = lane - 1;
                slot0 = 1 + (j / cw) * GRID_ + (c0 + j % cw);
            }
            if (lane + 32 < cnt) {
                const int j = lane + 31;
                slot1 = 1 + (j / cw) * GRID_ + (c0 + j % cw);
            }
            const __half* qrow = sQ + c * 64;
            const __half* k0r  = sK + slot0 * KSTRH;
            const __half* k1r  = sK + slot1 * KSTRH;
            float acc0 = 0.f, acc1 = 0.f;
#pragma unroll
            for (int i = 0; i < 8; i++) {
                const uint4 qv = *(const uint4*)(qrow + i * 8);
                const uint4 k0 = *(const uint4*)(k0r + i * 8);
                const uint4 k1 = *(const uint4*)(k1r + i * 8);
                const __half2* qh = (const __half2*)&qv;
                const __half2* kh0 = (const __half2*)&k0;
                const __half2* kh1 = (const __half2*)&k1;
#pragma unroll
                for (int w = 0; w < 4; w++) {
                    const float2 qf = __half22float2(qh[w]);
                    const float2 f0 = __half22float2(kh0[w]);
                    const float2 f1 = __half22float2(kh1[w]);
                    acc0 = fmaf(qf.x, f0.x, acc0);
                    acc0 = fmaf(qf.y, f0.y, acc0);
                    acc1 = fmaf(qf.x, f1.x, acc1);
                    acc1 = fmaf(qf.y, f1.y, acc1);
                }
            }
            float s0 = (lane < cnt)      ? acc0 * 0.125f : -1e30f;
            float s1 = (lane + 32 < cnt) ? acc1 * 0.125f : -1e30f;

            float mx = fmaxf(s0, s1);
#pragma unroll
            for (int off = 16; off; off >>= 1)
                mx = fmaxf(mx, __shfl_xor_sync(0xffffffffu, mx, off));
            const float e0 = __expf(s0 - mx);
            const float e1 = __expf(s1 - mx);
            float sum = e0 + e1;
#pragma unroll
            for (int off = 16; off; off >>= 1)
                sum += __shfl_xor_sync(0xffffffffu, sum, off);
            const float inv = 1.0f / sum;

            pack[c * 64 + lane]      = make_float2(e0 * inv, __int_as_float(slot0));
            pack[c * 64 + lane + 32] = make_float2(e1 * inv, __int_as_float(slot1));
        }
        __syncwarp();

        // ---- AV (no cross-warp dependency: each warp reads its own pack rows) ----
        for (int c = warp; c < GRID_; c += 8) {
            const int n = 1 + r * GRID_ + c;
            const size_t rowm = (size_t)b * N_ + n;
            const int c0 = (c - RAD_ < 0) ? 0 : c - RAD_;
            const int c1 = (c + RAD_ > GRID_ - 1) ? GRID_ - 1 : c + RAD_;
            const int cw = c1 - c0 + 1;
            const int cnt = 1 + span * cw;

            const float2* wp = pack + c * 64;
            float a0 = 0.f, a1 = 0.f;     // dims 2*lane, 2*lane+1
            for (int i = 0; i < cnt; i++) {
                const float2 ps = wp[i];
                const int slot = __float_as_int(ps.y);
                const __half2 vh = *(const __half2*)(sV + slot * KSTRH + 2 * lane);
                const float2 vf = __half22float2(vh);
                a0 = fmaf(ps.x, vf.x, a0);
                a1 = fmaf(ps.x, vf.y, a1);
            }

            const size_t o = rowm * C_ + h * D_ + 2 * lane;
            const __half h0 = __float2half(a0);
            const __half h1 = __float2half(a1);
            __half2 hp; hp.x = h0; hp.y = h1;
            __half2 lp;
            lp.x = __float2half(a0 - __half2float(h0));
            lp.y = __float2half(a1 - __half2float(h1));
            *(__half2*)(g_Ohi + o) = hp;
            *(__half2*)(g_Olo + o) = lp;
        }
    } else {
        // ---------------- CLS CTA ----------------
        float* sm     = (float*)smraw;
        float* scores = sm;                 // [577] (+pad)
        float* partA  = sm + 640;           // [8][64]
        float* red    = sm + 640 + 8 * 64;  // [8]

        const int w2 = blk - NLOCALBLK;
        const int b  = w2 / H_;
        const int h  = w2 % H_;

        const size_t rowm = (size_t)b * N_;   // n = 0
        const __half* qp = g_QKV + rowm * (3 * C_) + h * D_;
        const float q0 = __half2float(qp[lane]);
        const float q1 = __half2float(qp[lane + 32]);

        const size_t krow0 = (size_t)b * N_ * (3 * C_);
        const int koff = C_ + h * D_;
        const int voff = 2 * C_ + h * D_;

        for (int j = warp; j < N_; j += 8) {
            const __half* kp = g_QKV + krow0 + (size_t)j * (3 * C_) + koff;
            float s = q0 * __half2float(kp[lane]) + q1 * __half2float(kp[lane + 32]);
#pragma unroll
            for (int off = 16; off; off >>= 1)
                s += __shfl_xor_sync(0xffffffffu, s, off);
            if (lane == 0) scores[j] = s * 0.125f;
        }
        __syncthreads();

        float mx = -1e30f;
        for (int i = tid; i < N_; i += 256) mx = fmaxf(mx, scores[i]);
#pragma unroll
        for (int off = 16; off; off >>= 1)
            mx = fmaxf(mx, __shfl_xor_sync(0xffffffffu, mx, off));
        if (lane == 0) red[warp] = mx;
        __syncthreads();
        mx = red[0];
#pragma unroll
        for (int w = 1; w < 8; w++) mx = fmaxf(mx, red[w]);
        __syncthreads();

        float lsum = 0.f;
        for (int i = tid; i < N_; i += 256) {
            float e = __expf(scores[i] - mx);
            scores[i] = e;
            lsum += e;
        }
#pragma unroll
        for (int off = 16; off; off >>= 1)
            lsum += __shfl_xor_sync(0xffffffffu, lsum, off);
        if (lane == 0) red[warp] = lsum;
        __syncthreads();
        float sum = 0.f;
#pragma unroll
        for (int w = 0; w < 8; w++) sum += red[w];
        const float inv = 1.0f / sum;

        float a0 = 0.f, a1 = 0.f;
        for (int j = warp; j < N_; j += 8) {
            const float p = scores[j];
            const __half* vp = g_QKV + krow0 + (size_t)j * (3 * C_) + voff;
            a0 = fmaf(p, __half2float(vp[lane]),      a0);
            a1 = fmaf(p, __half2float(vp[lane + 32]), a1);
        }
        partA[warp * 64 + lane]      = a0;
        partA[warp * 64 + lane + 32] = a1;
        __syncthreads();

        if (warp == 0) {
            float t0 = 0.f, t1 = 0.f;
#pragma unroll
            for (int w = 0; w < 8; w++) {
                t0 += partA[w * 64 + lane];
                t1 += partA[w * 64 + lane + 32];
            }
            t0 *= inv; t1 *= inv;
            const size_t o = rowm * C_ + h * D_;
            const __half h0 = __float2half(t0);
            const __half h1 = __float2half(t1);
            g_Ohi[o + lane]      = h0;
            g_Olo[o + lane]      = __float2half(t0 - __half2float(h0));
            g_Ohi[o + lane + 32] = h1;
            g_Olo[o + lane + 32] = __float2half(t1 - __half2float(h1));
        }
    }
}

// ============================================================================
// launch
// ============================================================================
extern "C" void kernel_launch(void* const* d_in, const int* in_sizes, int n_in,
                              void* d_out, int out_size)
{
    const float* x     = (const float*)d_in[0];
    const float* Wqkv  = (const float*)d_in[1];
    const float* Wproj = (const float*)d_in[2];
    const float* bproj = (const float*)d_in[3];
    float* out = (float*)d_out;

    cudaFuncSetAttribute(hmma_gemm_kernel<0>,
                         cudaFuncAttributeMaxDynamicSharedMemorySize, GEMM_SMEM);
    cudaFuncSetAttribute(hmma_gemm_kernel<1>,
                         cudaFuncAttributeMaxDynamicSharedMemorySize, GEMM_SMEM);
    cudaFuncSetAttribute(attn_kernel,
                         cudaFuncAttributeMaxDynamicSharedMemorySize, ATT_SMEM);

    __half *xhi, *xlo, *whi, *phi, *ohi, *olo, *qkv;
    cudaGetSymbolAddress((void**)&xhi, g_xhi);
    cudaGetSymbolAddress((void**)&xlo, g_xlo);
    cudaGetSymbolAddress((void**)&whi, g_Whi);
    cudaGetSymbolAddress((void**)&phi, g_Phi);
    cudaGetSymbolAddress((void**)&ohi, g_Ohi);
    cudaGetSymbolAddress((void**)&olo, g_Olo);
    cudaGetSymbolAddress((void**)&qkv, g_QKV);

    // 0) conversions
    {
        size_t total = (size_t)MPAD_ * K_;
        conv_x_kernel<<<(unsigned)((total + 255) / 256), 256>>>(x);
        conv_wT_kernel<<<dim3(3 * C_ / 32, K_ / 32), 256>>>(Wqkv, whi, 3 * C_);
        conv_wT_kernel<<<dim3(C_ / 32, K_ / 32), 256>>>(Wproj, phi, C_);
    }

    // 1) QKV GEMM: [M,768] @ [2304,768]^T -> g_QKV (fp16)
    hmma_gemm_kernel<1><<<dim3(3 * C_ / 64, MT_), 256, GEMM_SMEM>>>(
        xhi, xlo, whi, nullptr, qkv, 3 * C_, M_);

    // 2) attention (local + CLS in one launch)
    attn_kernel<<<NLOCALBLK + B_ * H_, 256, ATT_SMEM>>>();

    // 3) proj GEMM: [M,768] @ [768,768]^T + bias -> out (fp32)
    hmma_gemm_kernel<0><<<dim3(C_ / 64, MT_), 256, GEMM_SMEM>>>(
        ohi, olo, phi, bproj, out, C_, M_);
}